// round 1
// baseline (speedup 1.0000x reference)
#include <cuda_runtime.h>
#include <cuda_bf16.h>
#include <math.h>

#define NN 100000
#define EE 1600000
#define GG 1000
#define FF 16
#define DD 128
#define CC 100
#define KK 2
#define LL 3

// ---------------- scratch (static device globals; no allocation) ----------------
__device__ float g_deg[NN];
__device__ float g_dinv[NN];
__device__ float g_h[(size_t)NN * DD];   // node features / aggregation buffer (in-place)
__device__ float g_m[(size_t)NN * DD];   // scaled messages m = dinv * (W h)
__device__ float g_pool[GG * CC];
__device__ float g_cnt[GG];

// ---------------- degree ----------------
__global__ void k_deg_init() {
    int i = blockIdx.x * blockDim.x + threadIdx.x;
    if (i < NN) g_deg[i] = 1.0f;  // self loop
}
__global__ void k_deg_acc(const int* __restrict__ dst) {
    int e = blockIdx.x * blockDim.x + threadIdx.x;
    if (e < EE) atomicAdd(&g_deg[dst[e]], 1.0f);
}
__global__ void k_dinv() {
    int i = blockIdx.x * blockDim.x + threadIdx.x;
    if (i < NN) g_dinv[i] = rsqrtf(fmaxf(g_deg[i], 1.0f));
}

// ---------------- embedding: h = x @ W_embed^T  ([N,16] -> [N,128]) ----------------
__global__ void k_embed(const float* __restrict__ x, const float* __restrict__ We) {
    __shared__ float wt[FF * DD];   // wt[f*128 + d] = We[d*16 + f]
    __shared__ float xs[32 * FF];
    int tid = threadIdx.x;
    for (int idx = tid; idx < DD * FF; idx += 256) {
        int d = idx >> 4, f = idx & 15;
        wt[f * DD + d] = We[idx];
    }
    int n0 = blockIdx.x * 32;
    for (int idx = tid; idx < 32 * FF; idx += 256) xs[idx] = x[(size_t)n0 * FF + idx];
    __syncthreads();
#pragma unroll
    for (int t = 0; t < 16; t++) {
        int idx = t * 256 + tid;
        int n = idx >> 7, d = idx & 127;
        float s = 0.f;
#pragma unroll
        for (int f = 0; f < FF; f++) s += xs[n * FF + f] * wt[f * DD + d];
        g_h[(size_t)(n0 + n) * DD + d] = s;
    }
}

// ---------------- GCN transform: m = dinv * (h @ W^T); h <- m (self-loop init) ----------------
// block: 256 threads, 64 rows. In-place safe: block only reads/writes its own rows.
__global__ void k_gemm(const float* __restrict__ W) {
    extern __shared__ float sm[];
    float* Wt = sm;                 // [128][129]  Wt[din*129 + dout]
    float* hs = sm + 128 * 129;     // [64][129]
    int tid = threadIdx.x;
    int n0 = blockIdx.x * 64;
    for (int idx = tid; idx < DD * DD; idx += 256) {
        int dout = idx >> 7, din = idx & 127;
        Wt[din * 129 + dout] = W[idx];
    }
    for (int idx = tid; idx < 64 * DD; idx += 256) {
        int r = idx >> 7, k = idx & 127;
        int n = n0 + r;
        hs[r * 129 + k] = (n < NN) ? g_h[(size_t)n * DD + k] : 0.f;
    }
    __syncthreads();

    int tx = tid & 15, ty = tid >> 4;   // tx: 8-col group, ty: 4-row group
    float acc[4][8];
#pragma unroll
    for (int i = 0; i < 4; i++)
#pragma unroll
        for (int j = 0; j < 8; j++) acc[i][j] = 0.f;

#pragma unroll 8
    for (int k = 0; k < 128; k++) {
        float b[8];
#pragma unroll
        for (int j = 0; j < 8; j++) b[j] = Wt[k * 129 + tx * 8 + j];
#pragma unroll
        for (int i = 0; i < 4; i++) {
            float a = hs[(ty * 4 + i) * 129 + k];
#pragma unroll
            for (int j = 0; j < 8; j++) acc[i][j] = fmaf(a, b[j], acc[i][j]);
        }
    }

#pragma unroll
    for (int i = 0; i < 4; i++) {
        int n = n0 + ty * 4 + i;
        if (n < NN) {
            float sc = g_dinv[n];
            size_t base = (size_t)n * DD + tx * 8;
#pragma unroll
            for (int j = 0; j < 8; j++) {
                float v = acc[i][j] * sc;
                g_m[base + j] = v;
                g_h[base + j] = v;   // self-loop contribution initializes accumulator
            }
        }
    }
}

// ---------------- scatter: h[dst] += m[src]  (warp per edge, float4 per lane) ----------------
__global__ void k_scatter(const int* __restrict__ src, const int* __restrict__ dst) {
    int gid = blockIdx.x * 256 + threadIdx.x;
    int e = gid >> 5, lane = gid & 31;
    if (e < EE) {
        int s = __ldg(src + e);
        int d = __ldg(dst + e);
        const float4 v = *(const float4*)(g_m + (size_t)s * DD + lane * 4);
        float* o = g_h + (size_t)d * DD + lane * 4;
        atomicAdd(o + 0, v.x);
        atomicAdd(o + 1, v.y);
        atomicAdd(o + 2, v.z);
        atomicAdd(o + 3, v.w);
    }
}

// ---------------- finalize: h = relu(dinv[v] * h) ----------------
__global__ void k_relu() {
    int i = blockIdx.x * blockDim.x + threadIdx.x;   // float4 index
    if (i < NN * (DD / 4)) {
        float sc = g_dinv[i >> 5];
        float4 v = ((float4*)g_h)[i];
        v.x = fmaxf(v.x * sc, 0.f);
        v.y = fmaxf(v.y * sc, 0.f);
        v.z = fmaxf(v.z * sc, 0.f);
        v.w = fmaxf(v.w * sc, 0.f);
        ((float4*)g_h)[i] = v;
    }
}

// ---------------- pooling prep ----------------
__global__ void k_zero_pool() {
    int i = blockIdx.x * blockDim.x + threadIdx.x;
    if (i < GG * CC) g_pool[i] = 0.f;
    if (i < GG) g_cnt[i] = 0.f;
}
__global__ void k_cnt(const int* __restrict__ batch) {
    int i = blockIdx.x * blockDim.x + threadIdx.x;
    if (i < NN) atomicAdd(&g_cnt[batch[i]], 1.0f);
}

// ---------------- distance to centroids + pooled sum ----------------
// block: 256 threads, 32 nodes. dist[n][c] = sqrt(sum_k (h-c)^2 + 1e-12); atomicAdd into pool.
__global__ void k_distpool(const float* __restrict__ cent, const int* __restrict__ batch) {
    extern __shared__ float sm[];
    float* ct = sm;                 // [128][132]  ct[k*132 + c], c padded to 128 (zeros)
    float* hs = ct + 128 * 132;     // [32][129]
    int tid = threadIdx.x;
    int n0 = blockIdx.x * 32;
    for (int idx = tid; idx < 128 * 132; idx += 256) ct[idx] = 0.f;
    __syncthreads();
    for (int idx = tid; idx < CC * DD; idx += 256) {
        int c = idx >> 7, k = idx & 127;
        ct[k * 132 + c] = cent[idx];
    }
    for (int idx = tid; idx < 32 * DD; idx += 256) {
        int r = idx >> 7, k = idx & 127;
        hs[r * 129 + k] = g_h[(size_t)(n0 + r) * DD + k];
    }
    __syncthreads();

    int tx = tid & 15, ty = tid >> 4;   // tx: 8-c group (128 padded), ty: 2-node group
    float acc[2][8];
#pragma unroll
    for (int i = 0; i < 2; i++)
#pragma unroll
        for (int j = 0; j < 8; j++) acc[i][j] = 0.f;

#pragma unroll 8
    for (int k = 0; k < 128; k++) {
        float b[8];
#pragma unroll
        for (int j = 0; j < 8; j++) b[j] = ct[k * 132 + tx * 8 + j];
#pragma unroll
        for (int i = 0; i < 2; i++) {
            float a = hs[(ty * 2 + i) * 129 + k];
#pragma unroll
            for (int j = 0; j < 8; j++) {
                float dlt = a - b[j];
                acc[i][j] = fmaf(dlt, dlt, acc[i][j]);
            }
        }
    }

#pragma unroll
    for (int i = 0; i < 2; i++) {
        int n = n0 + ty * 2 + i;
        int g = batch[n];
#pragma unroll
        for (int j = 0; j < 8; j++) {
            int c = tx * 8 + j;
            if (c < CC) atomicAdd(&g_pool[g * CC + c], sqrtf(acc[i][j] + 1e-12f));
        }
    }
}

// ---------------- output: out = (pool/cnt) @ W_out^T + b ----------------
__global__ void k_out(const float* __restrict__ Wout, const float* __restrict__ bout,
                      float* __restrict__ out) {
    int i = blockIdx.x * blockDim.x + threadIdx.x;
    if (i < GG * KK) {
        int g = i / KK, k = i % KK;
        float inv = 1.0f / fmaxf(g_cnt[g], 1.0f);
        float s = bout[k];
#pragma unroll 4
        for (int c = 0; c < CC; c++) s += g_pool[g * CC + c] * Wout[k * CC + c];
        out[i] = s * 0.f + (bout[k] + (s - bout[k]) * 1.f);  // keep exact: s already includes bias
    }
}

// corrected simple version (avoid the no-op above confusing anyone): recompute cleanly
__global__ void k_out2(const float* __restrict__ Wout, const float* __restrict__ bout,
                       float* __restrict__ out) {
    int i = blockIdx.x * blockDim.x + threadIdx.x;
    if (i < GG * KK) {
        int g = i / KK, k = i % KK;
        float inv = 1.0f / fmaxf(g_cnt[g], 1.0f);
        float s = 0.f;
#pragma unroll 4
        for (int c = 0; c < CC; c++) s += g_pool[g * CC + c] * Wout[k * CC + c];
        out[i] = s * inv + bout[k];
    }
}

extern "C" void kernel_launch(void* const* d_in, const int* in_sizes, int n_in,
                              void* d_out, int out_size) {
    const float* x     = (const float*)d_in[0];
    const int*   ei    = (const int*)d_in[1];     // [2, E]
    const int*   batch = (const int*)d_in[2];
    const float* We    = (const float*)d_in[3];   // [128,16]
    const float* Wc    = (const float*)d_in[4];   // [3,128,128]
    const float* cent  = (const float*)d_in[5];   // [100,128]
    const float* Wout  = (const float*)d_in[6];   // [2,100]
    const float* bout  = (const float*)d_in[7];   // [2]
    float* out = (float*)d_out;

    const int* src = ei;
    const int* dst = ei + EE;

    static bool attr_done = false;
    // (idempotent; executes immediately, not a graph node)
    cudaFuncSetAttribute(k_gemm, cudaFuncAttributeMaxDynamicSharedMemorySize,
                         (128 * 129 + 64 * 129) * 4);
    cudaFuncSetAttribute(k_distpool, cudaFuncAttributeMaxDynamicSharedMemorySize,
                         (128 * 132 + 32 * 129) * 4);
    (void)attr_done;

    const int T = 256;
    // degrees
    k_deg_init<<<(NN + T - 1) / T, T>>>();
    k_deg_acc<<<(EE + T - 1) / T, T>>>(dst);
    k_dinv<<<(NN + T - 1) / T, T>>>();

    // embedding
    k_embed<<<NN / 32, T>>>(x, We);

    // 3 GCN layers
    for (int l = 0; l < LL; l++) {
        k_gemm<<<(NN + 63) / 64, T, (128 * 129 + 64 * 129) * 4>>>(Wc + (size_t)l * DD * DD);
        k_scatter<<<(EE * 32 + T - 1) / T, T>>>(src, dst);
        k_relu<<<(NN * (DD / 4) + T - 1) / T, T>>>();
    }

    // pooling + distances
    k_zero_pool<<<(GG * CC + T - 1) / T, T>>>();
    k_cnt<<<(NN + T - 1) / T, T>>>(batch);
    k_distpool<<<NN / 32, T, (128 * 132 + 32 * 129) * 4>>>(cent, batch);

    // classifier
    k_out2<<<(GG * KK + T - 1) / T, T>>>(Wout, bout, out);
}

// round 3
// speedup vs baseline: 1.9906x; 1.9906x over previous
#include <cuda_runtime.h>
#include <cuda_bf16.h>
#include <math.h>

#define NN 100000
#define EE 1600000
#define GG 1000
#define FF 16
#define DD 128
#define CC 100
#define KK 2
#define LL 3

#define SCB 512
#define NB  ((NN + SCB - 1) / SCB)   // 196 scan blocks

// ---------------- scratch (static device globals; no allocation) ----------------
__device__ float g_dinv[NN];
__device__ float g_h[(size_t)NN * DD];   // node features (output of each layer)
__device__ float g_m[(size_t)NN * DD];   // scaled messages m = dinv * (W h)
__device__ float g_pool[GG * CC];
__device__ float g_cnt[GG];
__device__ int   g_cnti[NN];             // in-degree (excl self loop)
__device__ int   g_rowptr[NN + 1];
__device__ int   g_cursor[NN];
__device__ int   g_bsum[NB];
__device__ int   g_csr[EE];              // src ids bucketed by dst

// ---------------- zero counts + pool ----------------
__global__ void k_zero() {
    int i = blockIdx.x * blockDim.x + threadIdx.x;
    if (i < NN) g_cnti[i] = 0;
    if (i < GG * CC) g_pool[i] = 0.f;
    if (i < GG) g_cnt[i] = 0.f;
}

// ---------------- histogram over dst ----------------
__global__ void k_count(const int* __restrict__ dst) {
    int e = blockIdx.x * blockDim.x + threadIdx.x;
    if (e < EE) atomicAdd(&g_cnti[dst[e]], 1);
}

// ---------------- dinv from degree (deg = count + 1 self loop) ----------------
__global__ void k_dinv() {
    int i = blockIdx.x * blockDim.x + threadIdx.x;
    if (i < NN) g_dinv[i] = rsqrtf((float)(g_cnti[i] + 1));
}

// ---------------- exclusive scan (3 kernels) ----------------
__global__ void k_scan_part() {
    __shared__ int s[SCB];
    int t = threadIdx.x;
    int i = blockIdx.x * SCB + t;
    int v = (i < NN) ? g_cnti[i] : 0;
    s[t] = v;
    __syncthreads();
#pragma unroll
    for (int off = 1; off < SCB; off <<= 1) {
        int x = (t >= off) ? s[t - off] : 0;
        __syncthreads();
        s[t] += x;
        __syncthreads();
    }
    if (i < NN) g_rowptr[i] = s[t] - v;          // exclusive within block
    if (t == SCB - 1) g_bsum[blockIdx.x] = s[t]; // block total
}
__global__ void k_scan_bsum() {
    __shared__ int s[256];
    int t = threadIdx.x;
    int v = (t < NB) ? g_bsum[t] : 0;
    s[t] = v;
    __syncthreads();
#pragma unroll
    for (int off = 1; off < 256; off <<= 1) {
        int x = (t >= off) ? s[t - off] : 0;
        __syncthreads();
        s[t] += x;
        __syncthreads();
    }
    if (t < NB) g_bsum[t] = s[t] - v;            // exclusive block offsets
}
__global__ void k_scan_add() {
    int i = blockIdx.x * blockDim.x + threadIdx.x;
    if (i < NN) {
        int r = g_rowptr[i] + g_bsum[i / SCB];
        g_rowptr[i] = r;
        g_cursor[i] = r;
    }
    if (i == 0) g_rowptr[NN] = EE;
}

// ---------------- CSR fill ----------------
__global__ void k_fill(const int* __restrict__ src, const int* __restrict__ dst) {
    int e = blockIdx.x * blockDim.x + threadIdx.x;
    if (e < EE) {
        int d = dst[e];
        int pos = atomicAdd(&g_cursor[d], 1);
        g_csr[pos] = src[e];
    }
}

// ---------------- embedding: h = x @ W_embed^T  ([N,16] -> [N,128]) ----------------
__global__ void k_embed(const float* __restrict__ x, const float* __restrict__ We) {
    __shared__ float wt[FF * DD];
    __shared__ float xs[32 * FF];
    int tid = threadIdx.x;
    for (int idx = tid; idx < DD * FF; idx += 256) {
        int d = idx >> 4, f = idx & 15;
        wt[f * DD + d] = We[idx];
    }
    int n0 = blockIdx.x * 32;
    for (int idx = tid; idx < 32 * FF; idx += 256) xs[idx] = x[(size_t)n0 * FF + idx];
    __syncthreads();
#pragma unroll
    for (int t = 0; t < 16; t++) {
        int idx = t * 256 + tid;
        int n = idx >> 7, d = idx & 127;
        float s = 0.f;
#pragma unroll
        for (int f = 0; f < FF; f++) s += xs[n * FF + f] * wt[f * DD + d];
        g_h[(size_t)(n0 + n) * DD + d] = s;
    }
}

// ---------------- GCN transform: m = dinv * (h @ W^T) ----------------
__global__ void k_gemm(const float* __restrict__ W) {
    extern __shared__ float sm[];
    float* Wt = sm;                 // [128][129]  Wt[din*129 + dout]
    float* hs = sm + 128 * 129;     // [64][129]
    int tid = threadIdx.x;
    int n0 = blockIdx.x * 64;
    for (int idx = tid; idx < DD * DD; idx += 256) {
        int dout = idx >> 7, din = idx & 127;
        Wt[din * 129 + dout] = W[idx];
    }
    for (int idx = tid; idx < 64 * DD; idx += 256) {
        int r = idx >> 7, k = idx & 127;
        int n = n0 + r;
        hs[r * 129 + k] = (n < NN) ? g_h[(size_t)n * DD + k] : 0.f;
    }
    __syncthreads();

    int tx = tid & 15, ty = tid >> 4;
    float acc[4][8];
#pragma unroll
    for (int i = 0; i < 4; i++)
#pragma unroll
        for (int j = 0; j < 8; j++) acc[i][j] = 0.f;

#pragma unroll 8
    for (int k = 0; k < 128; k++) {
        float b[8];
#pragma unroll
        for (int j = 0; j < 8; j++) b[j] = Wt[k * 129 + tx * 8 + j];
#pragma unroll
        for (int i = 0; i < 4; i++) {
            float a = hs[(ty * 4 + i) * 129 + k];
#pragma unroll
            for (int j = 0; j < 8; j++) acc[i][j] = fmaf(a, b[j], acc[i][j]);
        }
    }

#pragma unroll
    for (int i = 0; i < 4; i++) {
        int n = n0 + ty * 4 + i;
        if (n < NN) {
            float sc = g_dinv[n];
            size_t base = (size_t)n * DD + tx * 8;
#pragma unroll
            for (int j = 0; j < 8; j++) g_m[base + j] = acc[i][j] * sc;
        }
    }
}

// ---------------- gather: h[v] = relu(dinv[v] * (m[v] + sum_{u->v} m[u])) ----------------
// warp per node, float4 per lane (lane covers 4 of 128 dims)
__global__ void k_gather() {
    int w = (blockIdx.x * 256 + threadIdx.x) >> 5;
    int lane = threadIdx.x & 31;
    if (w >= NN) return;
    int beg = g_rowptr[w], end = g_rowptr[w + 1];
    const float4* M = (const float4*)g_m;
    float4 acc = M[(size_t)w * 32 + lane];   // self loop

    int i = beg;
    for (; i + 32 <= end; i += 32) {
        int nb = g_csr[i + lane];
#pragma unroll
        for (int j = 0; j < 32; j += 4) {
            int u0 = __shfl_sync(0xffffffffu, nb, j);
            int u1 = __shfl_sync(0xffffffffu, nb, j + 1);
            int u2 = __shfl_sync(0xffffffffu, nb, j + 2);
            int u3 = __shfl_sync(0xffffffffu, nb, j + 3);
            float4 v0 = M[(size_t)u0 * 32 + lane];
            float4 v1 = M[(size_t)u1 * 32 + lane];
            float4 v2 = M[(size_t)u2 * 32 + lane];
            float4 v3 = M[(size_t)u3 * 32 + lane];
            acc.x += (v0.x + v1.x) + (v2.x + v3.x);
            acc.y += (v0.y + v1.y) + (v2.y + v3.y);
            acc.z += (v0.z + v1.z) + (v2.z + v3.z);
            acc.w += (v0.w + v1.w) + (v2.w + v3.w);
        }
    }
    int rem = end - i;
    if (rem > 0) {
        int nb = (lane < rem) ? g_csr[i + lane] : 0;
        int j = 0;
        for (; j + 4 <= rem; j += 4) {
            int u0 = __shfl_sync(0xffffffffu, nb, j);
            int u1 = __shfl_sync(0xffffffffu, nb, j + 1);
            int u2 = __shfl_sync(0xffffffffu, nb, j + 2);
            int u3 = __shfl_sync(0xffffffffu, nb, j + 3);
            float4 v0 = M[(size_t)u0 * 32 + lane];
            float4 v1 = M[(size_t)u1 * 32 + lane];
            float4 v2 = M[(size_t)u2 * 32 + lane];
            float4 v3 = M[(size_t)u3 * 32 + lane];
            acc.x += (v0.x + v1.x) + (v2.x + v3.x);
            acc.y += (v0.y + v1.y) + (v2.y + v3.y);
            acc.z += (v0.z + v1.z) + (v2.z + v3.z);
            acc.w += (v0.w + v1.w) + (v2.w + v3.w);
        }
        for (; j < rem; j++) {
            int u = __shfl_sync(0xffffffffu, nb, j);
            float4 v = M[(size_t)u * 32 + lane];
            acc.x += v.x; acc.y += v.y; acc.z += v.z; acc.w += v.w;
        }
    }

    float sc = g_dinv[w];
    acc.x = fmaxf(acc.x * sc, 0.f);
    acc.y = fmaxf(acc.y * sc, 0.f);
    acc.z = fmaxf(acc.z * sc, 0.f);
    acc.w = fmaxf(acc.w * sc, 0.f);
    ((float4*)g_h)[(size_t)w * 32 + lane] = acc;
}

// ---------------- batch counts ----------------
__global__ void k_cnt(const int* __restrict__ batch) {
    int i = blockIdx.x * blockDim.x + threadIdx.x;
    if (i < NN) atomicAdd(&g_cnt[batch[i]], 1.0f);
}

// ---------------- distance to centroids + pooled sum ----------------
__global__ void k_distpool(const float* __restrict__ cent, const int* __restrict__ batch) {
    extern __shared__ float sm[];
    float* ct = sm;                 // [128][132]  ct[k*132 + c] (c padded to 128, zeros)
    float* hs = ct + 128 * 132;     // [32][129]
    int tid = threadIdx.x;
    int n0 = blockIdx.x * 32;
    for (int idx = tid; idx < 128 * 132; idx += 256) ct[idx] = 0.f;
    __syncthreads();
    for (int idx = tid; idx < CC * DD; idx += 256) {
        int c = idx >> 7, k = idx & 127;
        ct[k * 132 + c] = cent[idx];
    }
    for (int idx = tid; idx < 32 * DD; idx += 256) {
        int r = idx >> 7, k = idx & 127;
        hs[r * 129 + k] = g_h[(size_t)(n0 + r) * DD + k];
    }
    __syncthreads();

    int tx = tid & 15, ty = tid >> 4;
    float acc[2][8];
#pragma unroll
    for (int i = 0; i < 2; i++)
#pragma unroll
        for (int j = 0; j < 8; j++) acc[i][j] = 0.f;

#pragma unroll 8
    for (int k = 0; k < 128; k++) {
        float b[8];
#pragma unroll
        for (int j = 0; j < 8; j++) b[j] = ct[k * 132 + tx * 8 + j];
#pragma unroll
        for (int i = 0; i < 2; i++) {
            float a = hs[(ty * 2 + i) * 129 + k];
#pragma unroll
            for (int j = 0; j < 8; j++) {
                float dlt = a - b[j];
                acc[i][j] = fmaf(dlt, dlt, acc[i][j]);
            }
        }
    }

#pragma unroll
    for (int i = 0; i < 2; i++) {
        int n = n0 + ty * 2 + i;
        int g = batch[n];
#pragma unroll
        for (int j = 0; j < 8; j++) {
            int c = tx * 8 + j;
            if (c < CC) atomicAdd(&g_pool[g * CC + c], sqrtf(acc[i][j] + 1e-12f));
        }
    }
}

// ---------------- output: out = (pool/cnt) @ W_out^T + b ----------------
__global__ void k_out(const float* __restrict__ Wout, const float* __restrict__ bout,
                      float* __restrict__ out) {
    int i = blockIdx.x * blockDim.x + threadIdx.x;
    if (i < GG * KK) {
        int g = i / KK, k = i % KK;
        float inv = 1.0f / fmaxf(g_cnt[g], 1.0f);
        float s = 0.f;
#pragma unroll 4
        for (int c = 0; c < CC; c++) s += g_pool[g * CC + c] * Wout[k * CC + c];
        out[i] = s * inv + bout[k];
    }
}

extern "C" void kernel_launch(void* const* d_in, const int* in_sizes, int n_in,
                              void* d_out, int out_size) {
    const float* x     = (const float*)d_in[0];
    const int*   ei    = (const int*)d_in[1];
    const int*   batch = (const int*)d_in[2];
    const float* We    = (const float*)d_in[3];
    const float* Wc    = (const float*)d_in[4];
    const float* cent  = (const float*)d_in[5];
    const float* Wout  = (const float*)d_in[6];
    const float* bout  = (const float*)d_in[7];
    float* out = (float*)d_out;

    const int* src = ei;
    const int* dst = ei + EE;

    cudaFuncSetAttribute(k_gemm, cudaFuncAttributeMaxDynamicSharedMemorySize,
                         (128 * 129 + 64 * 129) * 4);
    cudaFuncSetAttribute(k_distpool, cudaFuncAttributeMaxDynamicSharedMemorySize,
                         (128 * 132 + 32 * 129) * 4);

    const int T = 256;
    int zmax = (NN > GG * CC) ? NN : GG * CC;
    // zero + CSR build + dinv
    k_zero<<<(zmax + T - 1) / T, T>>>();
    k_count<<<(EE + T - 1) / T, T>>>(dst);
    k_dinv<<<(NN + T - 1) / T, T>>>();
    k_scan_part<<<NB, SCB>>>();
    k_scan_bsum<<<1, 256>>>();
    k_scan_add<<<(NN + T - 1) / T, T>>>();
    k_fill<<<(EE + T - 1) / T, T>>>(src, dst);

    // embedding
    k_embed<<<NN / 32, T>>>(x, We);

    // 3 GCN layers: gemm -> gather(+relu)
    for (int l = 0; l < LL; l++) {
        k_gemm<<<(NN + 63) / 64, T, (128 * 129 + 64 * 129) * 4>>>(Wc + (size_t)l * DD * DD);
        k_gather<<<(NN * 32 + T - 1) / T, T>>>();
    }

    // pooling + distances
    k_cnt<<<(NN + T - 1) / T, T>>>(batch);
    k_distpool<<<NN / 32, T, (128 * 132 + 32 * 129) * 4>>>(cent, batch);

    // classifier
    k_out<<<(GG * KK + T - 1) / T, T>>>(Wout, bout, out);
}

// round 5
// speedup vs baseline: 3.8340x; 1.9261x over previous
#include <cuda_runtime.h>
#include <cuda_bf16.h>
#include <math.h>

#define NN 100000
#define EE 1600000
#define GG 1000
#define FF 16
#define DD 128
#define CC 100
#define KK 2
#define LL 3

#define SCB 512
#define NB  ((NN + SCB - 1) / SCB)

// ---------------- scratch ----------------
__device__ float g_dinv[NN];
__device__ float g_h[(size_t)NN * DD];
__device__ float g_m[(size_t)NN * DD];
__device__ float g_pool[GG * CC];
__device__ float g_cnt[GG];
__device__ float g_wf[DD * FF];          // folded W1 @ W_embed
__device__ int   g_cnti[NN];
__device__ int   g_rowptr[NN + 1];
__device__ int   g_cursor[NN];
__device__ int   g_bsum[NB];
__device__ int   g_csr[EE];

// ---------------- zero ----------------
__global__ void k_zero() {
    int i = blockIdx.x * blockDim.x + threadIdx.x;
    if (i < NN) g_cnti[i] = 0;
    if (i < GG * CC) g_pool[i] = 0.f;
    if (i < GG) g_cnt[i] = 0.f;
}

// ---------------- CSR build ----------------
__global__ void k_count(const int* __restrict__ dst) {
    int e = blockIdx.x * blockDim.x + threadIdx.x;
    if (e < EE) atomicAdd(&g_cnti[dst[e]], 1);
}
__global__ void k_dinv() {
    int i = blockIdx.x * blockDim.x + threadIdx.x;
    if (i < NN) g_dinv[i] = rsqrtf((float)(g_cnti[i] + 1));
}
__global__ void k_scan_part() {
    __shared__ int s[SCB];
    int t = threadIdx.x;
    int i = blockIdx.x * SCB + t;
    int v = (i < NN) ? g_cnti[i] : 0;
    s[t] = v;
    __syncthreads();
#pragma unroll
    for (int off = 1; off < SCB; off <<= 1) {
        int x = (t >= off) ? s[t - off] : 0;
        __syncthreads();
        s[t] += x;
        __syncthreads();
    }
    if (i < NN) g_rowptr[i] = s[t] - v;
    if (t == SCB - 1) g_bsum[blockIdx.x] = s[t];
}
__global__ void k_scan_bsum() {
    __shared__ int s[256];
    int t = threadIdx.x;
    int v = (t < NB) ? g_bsum[t] : 0;
    s[t] = v;
    __syncthreads();
#pragma unroll
    for (int off = 1; off < 256; off <<= 1) {
        int x = (t >= off) ? s[t - off] : 0;
        __syncthreads();
        s[t] += x;
        __syncthreads();
    }
    if (t < NB) g_bsum[t] = s[t] - v;
}
__global__ void k_scan_add() {
    int i = blockIdx.x * blockDim.x + threadIdx.x;
    if (i < NN) {
        int r = g_rowptr[i] + g_bsum[i / SCB];
        g_rowptr[i] = r;
        g_cursor[i] = r;
    }
    if (i == 0) g_rowptr[NN] = EE;
}
__global__ void k_fill(const int* __restrict__ src, const int* __restrict__ dst) {
    int e = blockIdx.x * blockDim.x + threadIdx.x;
    if (e < EE) {
        int d = dst[e];
        int pos = atomicAdd(&g_cursor[d], 1);
        g_csr[pos] = src[e];
    }
}

// ---------------- fold: Wf = W1 @ We   ([128,128]x[128,16]) ----------------
__global__ void k_fold(const float* __restrict__ W1, const float* __restrict__ We) {
    __shared__ float we[DD * FF];
    int tid = threadIdx.x;
    for (int i = tid; i < DD * FF; i += 512) we[i] = We[i];
    __syncthreads();
    for (int i = tid; i < DD * FF; i += 512) {
        int d = i >> 4, f = i & 15;
        float s = 0.f;
#pragma unroll 8
        for (int k = 0; k < DD; k++) s += W1[d * DD + k] * we[k * FF + f];
        g_wf[i] = s;
    }
}

// ---------------- layer0 transform: m = dinv * (x @ Wf^T) ----------------
__global__ void k_gemm16(const float* __restrict__ x) {
    __shared__ float wt[FF * DD];   // wt[f*128 + d]
    __shared__ float xs[32 * FF];
    int tid = threadIdx.x;
    for (int idx = tid; idx < DD * FF; idx += 256) {
        int d = idx >> 4, f = idx & 15;
        wt[f * DD + d] = g_wf[idx];
    }
    int n0 = blockIdx.x * 32;
    for (int idx = tid; idx < 32 * FF; idx += 256) xs[idx] = x[(size_t)n0 * FF + idx];
    __syncthreads();
#pragma unroll
    for (int t = 0; t < 16; t++) {
        int idx = t * 256 + tid;
        int n = idx >> 7, d = idx & 127;
        float s = 0.f;
#pragma unroll
        for (int f = 0; f < FF; f++) s += xs[n * FF + f] * wt[f * DD + d];
        g_m[(size_t)(n0 + n) * DD + d] = s * g_dinv[n0 + n];
    }
}

// ---------------- GCN transform: m = dinv * (h @ W^T)  (128x128 tile, 8x8/thread) ----------------
#define KC 32
#define PAD 36
__global__ void __launch_bounds__(256, 2) k_gemm(const float* __restrict__ W) {
    __shared__ float Ws[DD][PAD];   // Ws[dout][kk]
    __shared__ float hs[DD][PAD];   // hs[row][kk]
    int tid = threadIdx.x;
    int tx = tid & 15, ty = tid >> 4;
    int n0 = blockIdx.x * 128;

    float acc[8][8];
#pragma unroll
    for (int i = 0; i < 8; i++)
#pragma unroll
        for (int j = 0; j < 8; j++) acc[i][j] = 0.f;

    for (int kc = 0; kc < DD; kc += KC) {
        for (int idx = tid; idx < DD * KC; idx += 256) {
            int r = idx >> 5, kk = idx & 31;
            Ws[r][kk] = W[r * DD + kc + kk];
            int n = n0 + r;
            hs[r][kk] = (n < NN) ? g_h[(size_t)n * DD + kc + kk] : 0.f;
        }
        __syncthreads();
#pragma unroll
        for (int kq = 0; kq < KC / 4; kq++) {
            float4 a4[8];
#pragma unroll
            for (int i = 0; i < 8; i++)
                a4[i] = *(const float4*)&hs[ty * 8 + i][kq * 4];
#pragma unroll
            for (int j = 0; j < 8; j++) {
                float4 b4 = *(const float4*)&Ws[tx + 16 * j][kq * 4];
#pragma unroll
                for (int i = 0; i < 8; i++) {
                    acc[i][j] = fmaf(a4[i].x, b4.x, acc[i][j]);
                    acc[i][j] = fmaf(a4[i].y, b4.y, acc[i][j]);
                    acc[i][j] = fmaf(a4[i].z, b4.z, acc[i][j]);
                    acc[i][j] = fmaf(a4[i].w, b4.w, acc[i][j]);
                }
            }
        }
        __syncthreads();
    }

#pragma unroll
    for (int i = 0; i < 8; i++) {
        int n = n0 + ty * 8 + i;
        if (n < NN) {
            float sc = g_dinv[n];
            size_t base = (size_t)n * DD;
#pragma unroll
            for (int j = 0; j < 8; j++) g_m[base + tx + 16 * j] = acc[i][j] * sc;
        }
    }
}

// ---------------- gather: h[v] = relu(dinv[v] * (m[v] + sum m[u])) ----------------
__global__ void k_gather() {
    int w = (blockIdx.x * 256 + threadIdx.x) >> 5;
    int lane = threadIdx.x & 31;
    if (w >= NN) return;
    int beg = g_rowptr[w], end = g_rowptr[w + 1];
    const float4* M = (const float4*)g_m;
    float4 acc = M[(size_t)w * 32 + lane];
    float4 acc2 = make_float4(0.f, 0.f, 0.f, 0.f);

    int i = beg;
    int cnt = end - beg;
    while (cnt > 0) {
        int take = cnt > 32 ? 32 : cnt;
        int nb = (lane < take) ? g_csr[i + lane] : 0;
        int j = 0;
        for (; j + 8 <= take; j += 8) {
            int u0 = __shfl_sync(0xffffffffu, nb, j);
            int u1 = __shfl_sync(0xffffffffu, nb, j + 1);
            int u2 = __shfl_sync(0xffffffffu, nb, j + 2);
            int u3 = __shfl_sync(0xffffffffu, nb, j + 3);
            int u4 = __shfl_sync(0xffffffffu, nb, j + 4);
            int u5 = __shfl_sync(0xffffffffu, nb, j + 5);
            int u6 = __shfl_sync(0xffffffffu, nb, j + 6);
            int u7 = __shfl_sync(0xffffffffu, nb, j + 7);
            float4 v0 = M[(size_t)u0 * 32 + lane];
            float4 v1 = M[(size_t)u1 * 32 + lane];
            float4 v2 = M[(size_t)u2 * 32 + lane];
            float4 v3 = M[(size_t)u3 * 32 + lane];
            float4 v4 = M[(size_t)u4 * 32 + lane];
            float4 v5 = M[(size_t)u5 * 32 + lane];
            float4 v6 = M[(size_t)u6 * 32 + lane];
            float4 v7 = M[(size_t)u7 * 32 + lane];
            acc.x += (v0.x + v1.x) + (v2.x + v3.x);
            acc.y += (v0.y + v1.y) + (v2.y + v3.y);
            acc.z += (v0.z + v1.z) + (v2.z + v3.z);
            acc.w += (v0.w + v1.w) + (v2.w + v3.w);
            acc2.x += (v4.x + v5.x) + (v6.x + v7.x);
            acc2.y += (v4.y + v5.y) + (v6.y + v7.y);
            acc2.z += (v4.z + v5.z) + (v6.z + v7.z);
            acc2.w += (v4.w + v5.w) + (v6.w + v7.w);
        }
        for (; j < take; j++) {
            int u = __shfl_sync(0xffffffffu, nb, j);
            float4 v = M[(size_t)u * 32 + lane];
            acc2.x += v.x; acc2.y += v.y; acc2.z += v.z; acc2.w += v.w;
        }
        i += take;
        cnt -= take;
    }
    acc.x += acc2.x; acc.y += acc2.y; acc.z += acc2.z; acc.w += acc2.w;

    float sc = g_dinv[w];
    acc.x = fmaxf(acc.x * sc, 0.f);
    acc.y = fmaxf(acc.y * sc, 0.f);
    acc.z = fmaxf(acc.z * sc, 0.f);
    acc.w = fmaxf(acc.w * sc, 0.f);
    ((float4*)g_h)[(size_t)w * 32 + lane] = acc;
}

// ---------------- batch counts ----------------
__global__ void k_cnt(const int* __restrict__ batch) {
    int i = blockIdx.x * blockDim.x + threadIdx.x;
    if (i < NN) atomicAdd(&g_cnt[batch[i]], 1.0f);
}

// ---------------- distances + pool (GEMM form: d2 = x2 + c2 - 2 h.c) ----------------
__global__ void __launch_bounds__(256, 2) k_distpool(const float* __restrict__ cent,
                                                     const int* __restrict__ batch) {
    __shared__ float cs[DD][PAD];
    __shared__ float hs[DD][PAD];
    __shared__ float sx2[DD];
    __shared__ float sc2[DD];
    __shared__ int   sg[DD];
    int tid = threadIdx.x;
    int tx = tid & 15, ty = tid >> 4;
    int n0 = blockIdx.x * 128;

    if (tid < DD) {
        sx2[tid] = 0.f;
        sc2[tid] = 0.f;
        int n = n0 + tid;
        sg[tid] = (n < NN) ? batch[n] : -1;
    }

    float acc[8][8];
#pragma unroll
    for (int i = 0; i < 8; i++)
#pragma unroll
        for (int j = 0; j < 8; j++) acc[i][j] = 0.f;

    for (int kc = 0; kc < DD; kc += KC) {
        for (int idx = tid; idx < DD * KC; idx += 256) {
            int r = idx >> 5, kk = idx & 31;
            cs[r][kk] = (r < CC) ? cent[r * DD + kc + kk] : 0.f;
            int n = n0 + r;
            hs[r][kk] = (n < NN) ? g_h[(size_t)n * DD + kc + kk] : 0.f;
        }
        __syncthreads();
#pragma unroll
        for (int kq = 0; kq < KC / 4; kq++) {
            float4 a4[8];
#pragma unroll
            for (int i = 0; i < 8; i++)
                a4[i] = *(const float4*)&hs[ty * 8 + i][kq * 4];
#pragma unroll
            for (int j = 0; j < 8; j++) {
                float4 b4 = *(const float4*)&cs[tx + 16 * j][kq * 4];
#pragma unroll
                for (int i = 0; i < 8; i++) {
                    acc[i][j] = fmaf(a4[i].x, b4.x, acc[i][j]);
                    acc[i][j] = fmaf(a4[i].y, b4.y, acc[i][j]);
                    acc[i][j] = fmaf(a4[i].z, b4.z, acc[i][j]);
                    acc[i][j] = fmaf(a4[i].w, b4.w, acc[i][j]);
                }
            }
        }
        if (tid < DD) {
            float sh = 0.f, sc = 0.f;
#pragma unroll 8
            for (int kk = 0; kk < KC; kk++) {
                sh = fmaf(hs[tid][kk], hs[tid][kk], sh);
                sc = fmaf(cs[tid][kk], cs[tid][kk], sc);
            }
            sx2[tid] += sh;
            sc2[tid] += sc;
        }
        __syncthreads();
    }

#pragma unroll
    for (int j = 0; j < 8; j++) {
        int c = tx + 16 * j;
        if (c >= CC) continue;
        float c2v = sc2[c];
        int cur = -2;
        float s = 0.f;
#pragma unroll
        for (int i = 0; i < 8; i++) {
            int r = ty * 8 + i;
            int g = sg[r];
            if (g < 0) continue;
            float d2 = fmaxf(sx2[r] + c2v - 2.f * acc[i][j], 0.f);
            float v = sqrtf(d2 + 1e-12f);
            if (g == cur) s += v;
            else {
                if (cur >= 0) atomicAdd(&g_pool[cur * CC + c], s);
                cur = g; s = v;
            }
        }
        if (cur >= 0) atomicAdd(&g_pool[cur * CC + c], s);
    }
}

// ---------------- output ----------------
__global__ void k_out(const float* __restrict__ Wout, const float* __restrict__ bout,
                      float* __restrict__ out) {
    int i = blockIdx.x * blockDim.x + threadIdx.x;
    if (i < GG * KK) {
        int g = i / KK, k = i % KK;
        float inv = 1.0f / fmaxf(g_cnt[g], 1.0f);
        float s = 0.f;
#pragma unroll 4
        for (int c = 0; c < CC; c++) s += g_pool[g * CC + c] * Wout[k * CC + c];
        out[i] = s * inv + bout[k];
    }
}

extern "C" void kernel_launch(void* const* d_in, const int* in_sizes, int n_in,
                              void* d_out, int out_size) {
    const float* x     = (const float*)d_in[0];
    const int*   ei    = (const int*)d_in[1];
    const int*   batch = (const int*)d_in[2];
    const float* We    = (const float*)d_in[3];
    const float* Wc    = (const float*)d_in[4];
    const float* cent  = (const float*)d_in[5];
    const float* Wout  = (const float*)d_in[6];
    const float* bout  = (const float*)d_in[7];
    float* out = (float*)d_out;

    const int* src = ei;
    const int* dst = ei + EE;

    const int T = 256;
    int zmax = (NN > GG * CC) ? NN : GG * CC;
    const int GB = (NN + 127) / 128;

    k_zero<<<(zmax + T - 1) / T, T>>>();
    k_count<<<(EE + T - 1) / T, T>>>(dst);
    k_dinv<<<(NN + T - 1) / T, T>>>();
    k_scan_part<<<NB, SCB>>>();
    k_scan_bsum<<<1, 256>>>();
    k_scan_add<<<(NN + T - 1) / T, T>>>();
    k_fill<<<(EE + T - 1) / T, T>>>(src, dst);

    k_fold<<<1, 512>>>(Wc, We);
    k_gemm16<<<NN / 32, T>>>(x);
    k_gather<<<(NN * 32 + T - 1) / T, T>>>();

    for (int l = 1; l < LL; l++) {
        k_gemm<<<GB, T>>>(Wc + (size_t)l * DD * DD);
        k_gather<<<(NN * 32 + T - 1) / T, T>>>();
    }

    k_cnt<<<(NN + T - 1) / T, T>>>(batch);
    k_distpool<<<GB, T>>>(cent, batch);

    k_out<<<(GG * KK + T - 1) / T, T>>>(Wout, bout, out);
}

// round 7
// speedup vs baseline: 4.2327x; 1.1040x over previous
#include <cuda_runtime.h>
#include <cuda_bf16.h>
#include <cstdint>
#include <math.h>

typedef unsigned int u32;

#define NN 100000
#define EE 1600000
#define GG 1000
#define FF 16
#define DD 128
#define CC 100
#define KK 2
#define LL 3

#define SCB 512
#define NB  ((NN + SCB - 1) / SCB)

// ---------------- scratch ----------------
__device__ float g_dinv[NN];
__device__ float g_h[(size_t)NN * DD];
__device__ u32   g_mb[(size_t)NN * 64];   // messages, packed bf16x2 (64 words = 128 bf16 per row)
__device__ float g_pool[GG * CC];
__device__ float g_cnt[GG];
__device__ float g_wf[DD * FF];           // folded W1 @ W_embed
__device__ int   g_cnti[NN];
__device__ int   g_rowptr[NN + 1];
__device__ int   g_cursor[NN];
__device__ int   g_bsum[NB];
__device__ int   g_csr[EE];

__device__ __forceinline__ float2 bf2f(u32 u) {
    __nv_bfloat162 b = *(__nv_bfloat162*)&u;
    return __bfloat1622float2(b);
}

// ---------------- zero ----------------
__global__ void k_zero() {
    int i = blockIdx.x * blockDim.x + threadIdx.x;
    if (i < NN) g_cnti[i] = 0;
    if (i < GG * CC) g_pool[i] = 0.f;
    if (i < GG) g_cnt[i] = 0.f;
}

// ---------------- CSR build ----------------
__global__ void k_count(const int* __restrict__ dst) {
    int e = blockIdx.x * blockDim.x + threadIdx.x;
    if (e < EE) atomicAdd(&g_cnti[dst[e]], 1);
}
__global__ void k_dinv() {
    int i = blockIdx.x * blockDim.x + threadIdx.x;
    if (i < NN) g_dinv[i] = rsqrtf((float)(g_cnti[i] + 1));
}
__global__ void k_scan_part() {
    __shared__ int s[SCB];
    int t = threadIdx.x;
    int i = blockIdx.x * SCB + t;
    int v = (i < NN) ? g_cnti[i] : 0;
    s[t] = v;
    __syncthreads();
#pragma unroll
    for (int off = 1; off < SCB; off <<= 1) {
        int x = (t >= off) ? s[t - off] : 0;
        __syncthreads();
        s[t] += x;
        __syncthreads();
    }
    if (i < NN) g_rowptr[i] = s[t] - v;
    if (t == SCB - 1) g_bsum[blockIdx.x] = s[t];
}
__global__ void k_scan_bsum() {
    __shared__ int s[256];
    int t = threadIdx.x;
    int v = (t < NB) ? g_bsum[t] : 0;
    s[t] = v;
    __syncthreads();
#pragma unroll
    for (int off = 1; off < 256; off <<= 1) {
        int x = (t >= off) ? s[t - off] : 0;
        __syncthreads();
        s[t] += x;
        __syncthreads();
    }
    if (t < NB) g_bsum[t] = s[t] - v;
}
__global__ void k_scan_add() {
    int i = blockIdx.x * blockDim.x + threadIdx.x;
    if (i < NN) {
        int r = g_rowptr[i] + g_bsum[i / SCB];
        g_rowptr[i] = r;
        g_cursor[i] = r;
    }
    if (i == 0) g_rowptr[NN] = EE;
}
__global__ void k_fill(const int* __restrict__ src, const int* __restrict__ dst) {
    int e = blockIdx.x * blockDim.x + threadIdx.x;
    if (e < EE) {
        int d = dst[e];
        int pos = atomicAdd(&g_cursor[d], 1);
        g_csr[pos] = src[e];
    }
}

// ---------------- fold: Wf = W1 @ We ----------------
__global__ void k_fold(const float* __restrict__ W1, const float* __restrict__ We) {
    __shared__ float we[DD * FF];
    int tid = threadIdx.x;
    for (int i = tid; i < DD * FF; i += 512) we[i] = We[i];
    __syncthreads();
    for (int i = tid; i < DD * FF; i += 512) {
        int d = i >> 4, f = i & 15;
        float s = 0.f;
#pragma unroll 8
        for (int k = 0; k < DD; k++) s += W1[d * DD + k] * we[k * FF + f];
        g_wf[i] = s;
    }
}

// ---------------- layer0 transform: m = dinv * (x @ Wf^T), bf16 packed out ----------------
__global__ void k_gemm16(const float* __restrict__ x) {
    __shared__ float wt[FF * DD];   // wt[f*128 + d]
    __shared__ float xs[32 * FF];
    int tid = threadIdx.x;
    for (int idx = tid; idx < DD * FF; idx += 256) {
        int d = idx >> 4, f = idx & 15;
        wt[f * DD + d] = g_wf[idx];
    }
    int n0 = blockIdx.x * 32;
    for (int idx = tid; idx < 32 * FF; idx += 256) xs[idx] = x[(size_t)n0 * FF + idx];
    __syncthreads();

    int p = tid & 63;          // bf16x2 pair index: cols 2p, 2p+1
    int nb = tid >> 6;         // 4 nodes per pass
    int d0 = 2 * p;
#pragma unroll
    for (int it = 0; it < 8; it++) {
        int n = it * 4 + nb;
        float s0 = 0.f, s1 = 0.f;
#pragma unroll
        for (int f = 0; f < FF; f++) {
            float xv = xs[n * FF + f];
            s0 = fmaf(xv, wt[f * DD + d0], s0);
            s1 = fmaf(xv, wt[f * DD + d0 + 1], s1);
        }
        float sc = g_dinv[n0 + n];
        __nv_bfloat162 pk = __floats2bfloat162_rn(s0 * sc, s1 * sc);
        g_mb[(size_t)(n0 + n) * 64 + p] = *(u32*)&pk;
    }
}

// ---------------- GCN transform: m = dinv * (h @ W^T), bf16 packed out ----------------
#define KC 32
#define PAD 36
__global__ void __launch_bounds__(256, 2) k_gemm(const float* __restrict__ W) {
    __shared__ float Ws[DD][PAD];   // Ws[dout][kk]
    __shared__ float hs[DD][PAD];   // hs[row][kk]
    int tid = threadIdx.x;
    int tx = tid & 15, ty = tid >> 4;
    int n0 = blockIdx.x * 128;

    float acc[8][8];
#pragma unroll
    for (int i = 0; i < 8; i++)
#pragma unroll
        for (int j = 0; j < 8; j++) acc[i][j] = 0.f;

    for (int kc = 0; kc < DD; kc += KC) {
        for (int idx = tid; idx < DD * KC; idx += 256) {
            int r = idx >> 5, kk = idx & 31;
            Ws[r][kk] = W[r * DD + kc + kk];
            int n = n0 + r;
            hs[r][kk] = (n < NN) ? g_h[(size_t)n * DD + kc + kk] : 0.f;
        }
        __syncthreads();
#pragma unroll
        for (int kq = 0; kq < KC / 4; kq++) {
            float4 a4[8];
#pragma unroll
            for (int i = 0; i < 8; i++)
                a4[i] = *(const float4*)&hs[ty * 8 + i][kq * 4];
#pragma unroll
            for (int j = 0; j < 8; j++) {
                float4 b4 = *(const float4*)&Ws[tx + 16 * j][kq * 4];
#pragma unroll
                for (int i = 0; i < 8; i++) {
                    acc[i][j] = fmaf(a4[i].x, b4.x, acc[i][j]);
                    acc[i][j] = fmaf(a4[i].y, b4.y, acc[i][j]);
                    acc[i][j] = fmaf(a4[i].z, b4.z, acc[i][j]);
                    acc[i][j] = fmaf(a4[i].w, b4.w, acc[i][j]);
                }
            }
        }
        __syncthreads();
    }

    // epilogue: pair columns (tx, tx+1) via shfl, even tx emits bf16x2
#pragma unroll
    for (int i = 0; i < 8; i++) {
        int n = n0 + ty * 8 + i;
        float sc = (n < NN) ? g_dinv[n] : 0.f;
#pragma unroll
        for (int j = 0; j < 8; j++) {
            float v = acc[i][j] * sc;
            float o = __shfl_xor_sync(0xffffffffu, v, 1);
            if ((tx & 1) == 0 && n < NN) {
                __nv_bfloat162 pk = __floats2bfloat162_rn(v, o);
                g_mb[(size_t)n * 64 + (tx >> 1) + 8 * j] = *(u32*)&pk;
            }
        }
    }
}

// ---------------- gather: h[v] = relu(dinv[v] * (m[v] + sum m[u])), bf16 in / fp32 out ----------------
__global__ void k_gather() {
    int w = (blockIdx.x * 256 + threadIdx.x) >> 5;
    int lane = threadIdx.x & 31;
    if (w >= NN) return;
    int beg = g_rowptr[w], end = g_rowptr[w + 1];
    const uint2* M2 = (const uint2*)g_mb;     // row = 32 uint2; lane covers cols 4l..4l+3

    uint2 sr = M2[(size_t)w * 32 + lane];
    float2 sa = bf2f(sr.x), sb = bf2f(sr.y);
    float4 acc = make_float4(sa.x, sa.y, sb.x, sb.y);
    float4 acc2 = make_float4(0.f, 0.f, 0.f, 0.f);

    int i = beg;
    int cnt = end - beg;
    while (cnt > 0) {
        int take = cnt > 32 ? 32 : cnt;
        int nb = (lane < take) ? g_csr[i + lane] : 0;
        int j = 0;
        for (; j + 8 <= take; j += 8) {
            int u0 = __shfl_sync(0xffffffffu, nb, j);
            int u1 = __shfl_sync(0xffffffffu, nb, j + 1);
            int u2 = __shfl_sync(0xffffffffu, nb, j + 2);
            int u3 = __shfl_sync(0xffffffffu, nb, j + 3);
            int u4 = __shfl_sync(0xffffffffu, nb, j + 4);
            int u5 = __shfl_sync(0xffffffffu, nb, j + 5);
            int u6 = __shfl_sync(0xffffffffu, nb, j + 6);
            int u7 = __shfl_sync(0xffffffffu, nb, j + 7);
            uint2 r0 = M2[(size_t)u0 * 32 + lane];
            uint2 r1 = M2[(size_t)u1 * 32 + lane];
            uint2 r2 = M2[(size_t)u2 * 32 + lane];
            uint2 r3 = M2[(size_t)u3 * 32 + lane];
            uint2 r4 = M2[(size_t)u4 * 32 + lane];
            uint2 r5 = M2[(size_t)u5 * 32 + lane];
            uint2 r6 = M2[(size_t)u6 * 32 + lane];
            uint2 r7 = M2[(size_t)u7 * 32 + lane];
            float2 a0 = bf2f(r0.x), b0 = bf2f(r0.y);
            float2 a1 = bf2f(r1.x), b1 = bf2f(r1.y);
            float2 a2 = bf2f(r2.x), b2 = bf2f(r2.y);
            float2 a3 = bf2f(r3.x), b3 = bf2f(r3.y);
            float2 a4 = bf2f(r4.x), b4 = bf2f(r4.y);
            float2 a5 = bf2f(r5.x), b5 = bf2f(r5.y);
            float2 a6 = bf2f(r6.x), b6 = bf2f(r6.y);
            float2 a7 = bf2f(r7.x), b7 = bf2f(r7.y);
            acc.x += (a0.x + a1.x) + (a2.x + a3.x);
            acc.y += (a0.y + a1.y) + (a2.y + a3.y);
            acc.z += (b0.x + b1.x) + (b2.x + b3.x);
            acc.w += (b0.y + b1.y) + (b2.y + b3.y);
            acc2.x += (a4.x + a5.x) + (a6.x + a7.x);
            acc2.y += (a4.y + a5.y) + (a6.y + a7.y);
            acc2.z += (b4.x + b5.x) + (b6.x + b7.x);
            acc2.w += (b4.y + b5.y) + (b6.y + b7.y);
        }
        for (; j < take; j++) {
            int u = __shfl_sync(0xffffffffu, nb, j);
            uint2 r = M2[(size_t)u * 32 + lane];
            float2 a = bf2f(r.x), b = bf2f(r.y);
            acc2.x += a.x; acc2.y += a.y; acc2.z += b.x; acc2.w += b.y;
        }
        i += take;
        cnt -= take;
    }
    acc.x += acc2.x; acc.y += acc2.y; acc.z += acc2.z; acc.w += acc2.w;

    float sc = g_dinv[w];
    acc.x = fmaxf(acc.x * sc, 0.f);
    acc.y = fmaxf(acc.y * sc, 0.f);
    acc.z = fmaxf(acc.z * sc, 0.f);
    acc.w = fmaxf(acc.w * sc, 0.f);
    ((float4*)g_h)[(size_t)w * 32 + lane] = acc;
}

// ---------------- batch counts ----------------
__global__ void k_cnt(const int* __restrict__ batch) {
    int i = blockIdx.x * blockDim.x + threadIdx.x;
    if (i < NN) atomicAdd(&g_cnt[batch[i]], 1.0f);
}

// ---------------- distances + pool (d2 = x2 + c2 - 2 h.c) ----------------
__global__ void __launch_bounds__(256, 2) k_distpool(const float* __restrict__ cent,
                                                     const int* __restrict__ batch) {
    __shared__ float cs[DD][PAD];
    __shared__ float hs[DD][PAD];
    __shared__ float sx2[DD];
    __shared__ float sc2[DD];
    __shared__ int   sg[DD];
    int tid = threadIdx.x;
    int tx = tid & 15, ty = tid >> 4;
    int n0 = blockIdx.x * 128;

    if (tid < DD) {
        sx2[tid] = 0.f;
        sc2[tid] = 0.f;
        int n = n0 + tid;
        sg[tid] = (n < NN) ? batch[n] : -1;
    }

    float acc[8][8];
#pragma unroll
    for (int i = 0; i < 8; i++)
#pragma unroll
        for (int j = 0; j < 8; j++) acc[i][j] = 0.f;

    for (int kc = 0; kc < DD; kc += KC) {
        for (int idx = tid; idx < DD * KC; idx += 256) {
            int r = idx >> 5, kk = idx & 31;
            cs[r][kk] = (r < CC) ? cent[r * DD + kc + kk] : 0.f;
            int n = n0 + r;
            hs[r][kk] = (n < NN) ? g_h[(size_t)n * DD + kc + kk] : 0.f;
        }
        __syncthreads();
#pragma unroll
        for (int kq = 0; kq < KC / 4; kq++) {
            float4 a4[8];
#pragma unroll
            for (int i = 0; i < 8; i++)
                a4[i] = *(const float4*)&hs[ty * 8 + i][kq * 4];
#pragma unroll
            for (int j = 0; j < 8; j++) {
                float4 b4 = *(const float4*)&cs[tx + 16 * j][kq * 4];
#pragma unroll
                for (int i = 0; i < 8; i++) {
                    acc[i][j] = fmaf(a4[i].x, b4.x, acc[i][j]);
                    acc[i][j] = fmaf(a4[i].y, b4.y, acc[i][j]);
                    acc[i][j] = fmaf(a4[i].z, b4.z, acc[i][j]);
                    acc[i][j] = fmaf(a4[i].w, b4.w, acc[i][j]);
                }
            }
        }
        if (tid < DD) {
            float sh = 0.f, sc = 0.f;
#pragma unroll 8
            for (int kk = 0; kk < KC; kk++) {
                sh = fmaf(hs[tid][kk], hs[tid][kk], sh);
                sc = fmaf(cs[tid][kk], cs[tid][kk], sc);
            }
            sx2[tid] += sh;
            sc2[tid] += sc;
        }
        __syncthreads();
    }

#pragma unroll
    for (int j = 0; j < 8; j++) {
        int c = tx + 16 * j;
        if (c >= CC) continue;
        float c2v = sc2[c];
        int cur = -2;
        float s = 0.f;
#pragma unroll
        for (int i = 0; i < 8; i++) {
            int r = ty * 8 + i;
            int g = sg[r];
            if (g < 0) continue;
            float d2 = fmaxf(sx2[r] + c2v - 2.f * acc[i][j], 0.f);
            float v = sqrtf(d2 + 1e-12f);
            if (g == cur) s += v;
            else {
                if (cur >= 0) atomicAdd(&g_pool[cur * CC + c], s);
                cur = g; s = v;
            }
        }
        if (cur >= 0) atomicAdd(&g_pool[cur * CC + c], s);
    }
}

// ---------------- output ----------------
__global__ void k_out(const float* __restrict__ Wout, const float* __restrict__ bout,
                      float* __restrict__ out) {
    int i = blockIdx.x * blockDim.x + threadIdx.x;
    if (i < GG * KK) {
        int g = i / KK, k = i % KK;
        float inv = 1.0f / fmaxf(g_cnt[g], 1.0f);
        float s = 0.f;
#pragma unroll 4
        for (int c = 0; c < CC; c++) s += g_pool[g * CC + c] * Wout[k * CC + c];
        out[i] = s * inv + bout[k];
    }
}

extern "C" void kernel_launch(void* const* d_in, const int* in_sizes, int n_in,
                              void* d_out, int out_size) {
    const float* x     = (const float*)d_in[0];
    const int*   ei    = (const int*)d_in[1];
    const int*   batch = (const int*)d_in[2];
    const float* We    = (const float*)d_in[3];
    const float* Wc    = (const float*)d_in[4];
    const float* cent  = (const float*)d_in[5];
    const float* Wout  = (const float*)d_in[6];
    const float* bout  = (const float*)d_in[7];
    float* out = (float*)d_out;

    const int* src = ei;
    const int* dst = ei + EE;

    const int T = 256;
    int zmax = (NN > GG * CC) ? NN : GG * CC;
    const int GB = (NN + 127) / 128;

    k_zero<<<(zmax + T - 1) / T, T>>>();
    k_count<<<(EE + T - 1) / T, T>>>(dst);
    k_dinv<<<(NN + T - 1) / T, T>>>();
    k_scan_part<<<NB, SCB>>>();
    k_scan_bsum<<<1, 256>>>();
    k_scan_add<<<(NN + T - 1) / T, T>>>();
    k_fill<<<(EE + T - 1) / T, T>>>(src, dst);

    k_fold<<<1, 512>>>(Wc, We);
    k_gemm16<<<NN / 32, T>>>(x);
    k_gather<<<(NN * 32 + T - 1) / T, T>>>();

    for (int l = 1; l < LL; l++) {
        k_gemm<<<GB, T>>>(Wc + (size_t)l * DD * DD);
        k_gather<<<(NN * 32 + T - 1) / T, T>>>();
    }

    k_cnt<<<(NN + T - 1) / T, T>>>(batch);
    k_distpool<<<GB, T>>>(cent, batch);

    k_out<<<(GG * KK + T - 1) / T, T>>>(Wout, bout, out);
}

// round 10
// speedup vs baseline: 4.2928x; 1.0142x over previous
#include <cuda_runtime.h>
#include <cuda_bf16.h>
#include <cuda_fp8.h>
#include <cstdint>
#include <math.h>

typedef unsigned int u32;

#define NN 100000
#define EE 1600000
#define GG 1000
#define FF 16
#define DD 128
#define CC 100
#define KK 2
#define LL 3

#define SCB 512
#define NB  ((NN + SCB - 1) / SCB)

// ---------------- scratch ----------------
__device__ float g_dinv[NN];
__device__ float g_h[(size_t)NN * DD];
__device__ u32   g_mb[(size_t)NN * 32];   // messages, packed fp8(e4m3)x4 (32 words = 128 fp8 per row)
__device__ float g_pool[GG * CC];
__device__ float g_cnt[GG];
__device__ float g_wf[DD * FF];           // folded W1 @ W_embed
__device__ int   g_cnti[NN];
__device__ int   g_rowptr[NN + 1];
__device__ int   g_cursor[NN];
__device__ int   g_bsum[NB];
__device__ int   g_csr[EE];

__device__ __forceinline__ float4 fp8x4_to_f4(u32 u) {
    __nv_fp8x2_storage_t lo = (__nv_fp8x2_storage_t)(u & 0xffffu);
    __nv_fp8x2_storage_t hi = (__nv_fp8x2_storage_t)(u >> 16);
    __half2_raw h0 = __nv_cvt_fp8x2_to_halfraw2(lo, __NV_E4M3);
    __half2_raw h1 = __nv_cvt_fp8x2_to_halfraw2(hi, __NV_E4M3);
    float2 a = __half22float2(*(__half2*)&h0);
    float2 b = __half22float2(*(__half2*)&h1);
    return make_float4(a.x, a.y, b.x, b.y);
}
__device__ __forceinline__ u32 f4_to_fp8x4(float x, float y, float z, float w) {
    __nv_fp8x2_storage_t lo = __nv_cvt_float2_to_fp8x2(make_float2(x, y), __NV_SATFINITE, __NV_E4M3);
    __nv_fp8x2_storage_t hi = __nv_cvt_float2_to_fp8x2(make_float2(z, w), __NV_SATFINITE, __NV_E4M3);
    return (u32)lo | ((u32)hi << 16);
}

// ---------------- zero ----------------
__global__ void k_zero() {
    int i = blockIdx.x * blockDim.x + threadIdx.x;
    if (i < NN) g_cnti[i] = 0;
    if (i < GG * CC) g_pool[i] = 0.f;
    if (i < GG) g_cnt[i] = 0.f;
}

// ---------------- CSR build ----------------
__global__ void k_count(const int* __restrict__ dst) {
    int e = blockIdx.x * blockDim.x + threadIdx.x;
    if (e < EE) atomicAdd(&g_cnti[dst[e]], 1);
}
__global__ void k_dinv() {
    int i = blockIdx.x * blockDim.x + threadIdx.x;
    if (i < NN) g_dinv[i] = rsqrtf((float)(g_cnti[i] + 1));
}
__global__ void k_scan_part() {
    __shared__ int s[SCB];
    int t = threadIdx.x;
    int i = blockIdx.x * SCB + t;
    int v = (i < NN) ? g_cnti[i] : 0;
    s[t] = v;
    __syncthreads();
#pragma unroll
    for (int off = 1; off < SCB; off <<= 1) {
        int x = (t >= off) ? s[t - off] : 0;
        __syncthreads();
        s[t] += x;
        __syncthreads();
    }
    if (i < NN) g_rowptr[i] = s[t] - v;
    if (t == SCB - 1) g_bsum[blockIdx.x] = s[t];
}
__global__ void k_scan_bsum() {
    __shared__ int s[256];
    int t = threadIdx.x;
    int v = (t < NB) ? g_bsum[t] : 0;
    s[t] = v;
    __syncthreads();
#pragma unroll
    for (int off = 1; off < 256; off <<= 1) {
        int x = (t >= off) ? s[t - off] : 0;
        __syncthreads();
        s[t] += x;
        __syncthreads();
    }
    if (t < NB) g_bsum[t] = s[t] - v;
}
__global__ void k_scan_add() {
    int i = blockIdx.x * blockDim.x + threadIdx.x;
    if (i < NN) {
        int r = g_rowptr[i] + g_bsum[i / SCB];
        g_rowptr[i] = r;
        g_cursor[i] = r;
    }
    if (i == 0) g_rowptr[NN] = EE;
}
__global__ void k_fill(const int* __restrict__ src, const int* __restrict__ dst) {
    int e = blockIdx.x * blockDim.x + threadIdx.x;
    if (e < EE) {
        int d = dst[e];
        int pos = atomicAdd(&g_cursor[d], 1);
        g_csr[pos] = src[e];
    }
}

// ---------------- fold: Wf = W1 @ We ----------------
__global__ void k_fold(const float* __restrict__ W1, const float* __restrict__ We) {
    __shared__ float we[DD * FF];
    int tid = threadIdx.x;
    for (int i = tid; i < DD * FF; i += 512) we[i] = We[i];
    __syncthreads();
    for (int i = tid; i < DD * FF; i += 512) {
        int d = i >> 4, f = i & 15;
        float s = 0.f;
#pragma unroll 8
        for (int k = 0; k < DD; k++) s += W1[d * DD + k] * we[k * FF + f];
        g_wf[i] = s;
    }
}

// ---------------- layer0 transform: m = dinv * (x @ Wf^T), fp8 packed out ----------------
__global__ void k_gemm16(const float* __restrict__ x) {
    __shared__ float wt[FF * DD];   // wt[f*128 + d]
    __shared__ float xs[32 * FF];
    int tid = threadIdx.x;
    for (int idx = tid; idx < DD * FF; idx += 256) {
        int d = idx >> 4, f = idx & 15;
        wt[f * DD + d] = g_wf[idx];
    }
    int n0 = blockIdx.x * 32;
    for (int idx = tid; idx < 32 * FF; idx += 256) xs[idx] = x[(size_t)n0 * FF + idx];
    __syncthreads();

    int wix = tid & 31;        // word index: cols 4w..4w+3
    int nb = tid >> 5;         // 8 nodes per pass
    int d0 = 4 * wix;
#pragma unroll
    for (int it = 0; it < 4; it++) {
        int n = it * 8 + nb;
        float s0 = 0.f, s1 = 0.f, s2 = 0.f, s3 = 0.f;
#pragma unroll
        for (int f = 0; f < FF; f++) {
            float xv = xs[n * FF + f];
            s0 = fmaf(xv, wt[f * DD + d0], s0);
            s1 = fmaf(xv, wt[f * DD + d0 + 1], s1);
            s2 = fmaf(xv, wt[f * DD + d0 + 2], s2);
            s3 = fmaf(xv, wt[f * DD + d0 + 3], s3);
        }
        float sc = g_dinv[n0 + n];
        g_mb[(size_t)(n0 + n) * 32 + wix] = f4_to_fp8x4(s0 * sc, s1 * sc, s2 * sc, s3 * sc);
    }
}

// ---------------- GCN transform: m = dinv * (h @ W^T), fp8 packed out ----------------
#define KC 32
#define PAD 36
__global__ void __launch_bounds__(256, 2) k_gemm(const float* __restrict__ W) {
    __shared__ float Ws[DD][PAD];   // Ws[dout][kk]
    __shared__ float hs[DD][PAD];   // hs[row][kk]
    int tid = threadIdx.x;
    int tx = tid & 15, ty = tid >> 4;
    int n0 = blockIdx.x * 128;

    float acc[8][8];
#pragma unroll
    for (int i = 0; i < 8; i++)
#pragma unroll
        for (int j = 0; j < 8; j++) acc[i][j] = 0.f;

    for (int kc = 0; kc < DD; kc += KC) {
        for (int idx = tid; idx < DD * KC; idx += 256) {
            int r = idx >> 5, kk = idx & 31;
            Ws[r][kk] = W[r * DD + kc + kk];
            int n = n0 + r;
            hs[r][kk] = (n < NN) ? g_h[(size_t)n * DD + kc + kk] : 0.f;
        }
        __syncthreads();
#pragma unroll
        for (int kq = 0; kq < KC / 4; kq++) {
            float4 a4[8];
#pragma unroll
            for (int i = 0; i < 8; i++)
                a4[i] = *(const float4*)&hs[ty * 8 + i][kq * 4];
#pragma unroll
            for (int j = 0; j < 8; j++) {
                float4 b4 = *(const float4*)&Ws[tx + 16 * j][kq * 4];
#pragma unroll
                for (int i = 0; i < 8; i++) {
                    acc[i][j] = fmaf(a4[i].x, b4.x, acc[i][j]);
                    acc[i][j] = fmaf(a4[i].y, b4.y, acc[i][j]);
                    acc[i][j] = fmaf(a4[i].z, b4.z, acc[i][j]);
                    acc[i][j] = fmaf(a4[i].w, b4.w, acc[i][j]);
                }
            }
        }
        __syncthreads();
    }

    // epilogue: quad columns (tx..tx+3) via two shfl stages, tx%4==0 emits fp8x4
#pragma unroll
    for (int i = 0; i < 8; i++) {
        int n = n0 + ty * 8 + i;
        float sc = (n < NN) ? g_dinv[n] : 0.f;
#pragma unroll
        for (int j = 0; j < 8; j++) {
            float v = acc[i][j] * sc;
            float o1 = __shfl_xor_sync(0xffffffffu, v, 1);
            __nv_fp8x2_storage_t p2 =
                __nv_cvt_float2_to_fp8x2(make_float2(v, o1), __NV_SATFINITE, __NV_E4M3);
            u32 p2u = (u32)p2;
            u32 o2 = __shfl_xor_sync(0xffffffffu, p2u, 2);
            if ((tx & 3) == 0 && n < NN) {
                u32 wd = p2u | (o2 << 16);    // cols tx..tx+3
                g_mb[(size_t)n * 32 + (tx >> 2) + 4 * j] = wd;
            }
        }
    }
}

// ---------------- gather: h[v] = relu(dinv[v] * (m[v] + sum m[u])), fp8 in / fp32 out ----------------
__global__ void k_gather() {
    int w = (blockIdx.x * 256 + threadIdx.x) >> 5;
    int lane = threadIdx.x & 31;
    if (w >= NN) return;
    int beg = g_rowptr[w], end = g_rowptr[w + 1];
    const u32* M = g_mb;     // row = 32 u32; lane covers cols 4l..4l+3

    float4 acc = fp8x4_to_f4(M[(size_t)w * 32 + lane]);   // self loop
    float4 acc2 = make_float4(0.f, 0.f, 0.f, 0.f);

    int i = beg;
    int cnt = end - beg;
    while (cnt > 0) {
        int take = cnt > 32 ? 32 : cnt;
        int nb = (lane < take) ? g_csr[i + lane] : 0;
        int j = 0;
        for (; j + 8 <= take; j += 8) {
            int u0 = __shfl_sync(0xffffffffu, nb, j);
            int u1 = __shfl_sync(0xffffffffu, nb, j + 1);
            int u2 = __shfl_sync(0xffffffffu, nb, j + 2);
            int u3 = __shfl_sync(0xffffffffu, nb, j + 3);
            int u4 = __shfl_sync(0xffffffffu, nb, j + 4);
            int u5 = __shfl_sync(0xffffffffu, nb, j + 5);
            int u6 = __shfl_sync(0xffffffffu, nb, j + 6);
            int u7 = __shfl_sync(0xffffffffu, nb, j + 7);
            u32 r0 = M[(size_t)u0 * 32 + lane];
            u32 r1 = M[(size_t)u1 * 32 + lane];
            u32 r2 = M[(size_t)u2 * 32 + lane];
            u32 r3 = M[(size_t)u3 * 32 + lane];
            u32 r4 = M[(size_t)u4 * 32 + lane];
            u32 r5 = M[(size_t)u5 * 32 + lane];
            u32 r6 = M[(size_t)u6 * 32 + lane];
            u32 r7 = M[(size_t)u7 * 32 + lane];
            float4 v0 = fp8x4_to_f4(r0);
            float4 v1 = fp8x4_to_f4(r1);
            float4 v2 = fp8x4_to_f4(r2);
            float4 v3 = fp8x4_to_f4(r3);
            float4 v4 = fp8x4_to_f4(r4);
            float4 v5 = fp8x4_to_f4(r5);
            float4 v6 = fp8x4_to_f4(r6);
            float4 v7 = fp8x4_to_f4(r7);
            acc.x += (v0.x + v1.x) + (v2.x + v3.x);
            acc.y += (v0.y + v1.y) + (v2.y + v3.y);
            acc.z += (v0.z + v1.z) + (v2.z + v3.z);
            acc.w += (v0.w + v1.w) + (v2.w + v3.w);
            acc2.x += (v4.x + v5.x) + (v6.x + v7.x);
            acc2.y += (v4.y + v5.y) + (v6.y + v7.y);
            acc2.z += (v4.z + v5.z) + (v6.z + v7.z);
            acc2.w += (v4.w + v5.w) + (v6.w + v7.w);
        }
        for (; j < take; j++) {
            int u = __shfl_sync(0xffffffffu, nb, j);
            float4 v = fp8x4_to_f4(M[(size_t)u * 32 + lane]);
            acc2.x += v.x; acc2.y += v.y; acc2.z += v.z; acc2.w += v.w;
        }
        i += take;
        cnt -= take;
    }
    acc.x += acc2.x; acc.y += acc2.y; acc.z += acc2.z; acc.w += acc2.w;

    float sc = g_dinv[w];
    acc.x = fmaxf(acc.x * sc, 0.f);
    acc.y = fmaxf(acc.y * sc, 0.f);
    acc.z = fmaxf(acc.z * sc, 0.f);
    acc.w = fmaxf(acc.w * sc, 0.f);
    ((float4*)g_h)[(size_t)w * 32 + lane] = acc;
}

// ---------------- batch counts ----------------
__global__ void k_cnt(const int* __restrict__ batch) {
    int i = blockIdx.x * blockDim.x + threadIdx.x;
    if (i < NN) atomicAdd(&g_cnt[batch[i]], 1.0f);
}

// ---------------- distances + pool (d2 = x2 + c2 - 2 h.c) ----------------
__global__ void __launch_bounds__(256, 2) k_distpool(const float* __restrict__ cent,
                                                     const int* __restrict__ batch) {
    __shared__ float cs[DD][PAD];
    __shared__ float hs[DD][PAD];
    __shared__ float sx2[DD];
    __shared__ float sc2[DD];
    __shared__ int   sg[DD];
    int tid = threadIdx.x;
    int tx = tid & 15, ty = tid >> 4;
    int n0 = blockIdx.x * 128;

    if (tid < DD) {
        sx2[tid] = 0.f;
        sc2[tid] = 0.f;
        int n = n0 + tid;
        sg[tid] = (n < NN) ? batch[n] : -1;
    }

    float acc[8][8];
#pragma unroll
    for (int i = 0; i < 8; i++)
#pragma unroll
        for (int j = 0; j < 8; j++) acc[i][j] = 0.f;

    for (int kc = 0; kc < DD; kc += KC) {
        for (int idx = tid; idx < DD * KC; idx += 256) {
            int r = idx >> 5, kk = idx & 31;
            cs[r][kk] = (r < CC) ? cent[r * DD + kc + kk] : 0.f;
            int n = n0 + r;
            hs[r][kk] = (n < NN) ? g_h[(size_t)n * DD + kc + kk] : 0.f;
        }
        __syncthreads();
#pragma unroll
        for (int kq = 0; kq < KC / 4; kq++) {
            float4 a4[8];
#pragma unroll
            for (int i = 0; i < 8; i++)
                a4[i] = *(const float4*)&hs[ty * 8 + i][kq * 4];
#pragma unroll
            for (int j = 0; j < 8; j++) {
                float4 b4 = *(const float4*)&cs[tx + 16 * j][kq * 4];
#pragma unroll
                for (int i = 0; i < 8; i++) {
                    acc[i][j] = fmaf(a4[i].x, b4.x, acc[i][j]);
                    acc[i][j] = fmaf(a4[i].y, b4.y, acc[i][j]);
                    acc[i][j] = fmaf(a4[i].z, b4.z, acc[i][j]);
                    acc[i][j] = fmaf(a4[i].w, b4.w, acc[i][j]);
                }
            }
        }
        if (tid < DD) {
            float sh = 0.f, sc = 0.f;
#pragma unroll 8
            for (int kk = 0; kk < KC; kk++) {
                sh = fmaf(hs[tid][kk], hs[tid][kk], sh);
                sc = fmaf(cs[tid][kk], cs[tid][kk], sc);
            }
            sx2[tid] += sh;
            sc2[tid] += sc;
        }
        __syncthreads();
    }

#pragma unroll
    for (int j = 0; j < 8; j++) {
        int c = tx + 16 * j;
        if (c >= CC) continue;
        float c2v = sc2[c];
        int cur = -2;
        float s = 0.f;
#pragma unroll
        for (int i = 0; i < 8; i++) {
            int r = ty * 8 + i;
            int g = sg[r];
            if (g < 0) continue;
            float d2 = fmaxf(sx2[r] + c2v - 2.f * acc[i][j], 0.f);
            float v = sqrtf(d2 + 1e-12f);
            if (g == cur) s += v;
            else {
                if (cur >= 0) atomicAdd(&g_pool[cur * CC + c], s);
                cur = g; s = v;
            }
        }
        if (cur >= 0) atomicAdd(&g_pool[cur * CC + c], s);
    }
}

// ---------------- output ----------------
__global__ void k_out(const float* __restrict__ Wout, const float* __restrict__ bout,
                      float* __restrict__ out) {
    int i = blockIdx.x * blockDim.x + threadIdx.x;
    if (i < GG * KK) {
        int g = i / KK, k = i % KK;
        float inv = 1.0f / fmaxf(g_cnt[g], 1.0f);
        float s = 0.f;
#pragma unroll 4
        for (int c = 0; c < CC; c++) s += g_pool[g * CC + c] * Wout[k * CC + c];
        out[i] = s * inv + bout[k];
    }
}

extern "C" void kernel_launch(void* const* d_in, const int* in_sizes, int n_in,
                              void* d_out, int out_size) {
    const float* x     = (const float*)d_in[0];
    const int*   ei    = (const int*)d_in[1];
    const int*   batch = (const int*)d_in[2];
    const float* We    = (const float*)d_in[3];
    const float* Wc    = (const float*)d_in[4];
    const float* cent  = (const float*)d_in[5];
    const float* Wout  = (const float*)d_in[6];
    const float* bout  = (const float*)d_in[7];
    float* out = (float*)d_out;

    const int* src = ei;
    const int* dst = ei + EE;

    const int T = 256;
    int zmax = (NN > GG * CC) ? NN : GG * CC;
    const int GB = (NN + 127) / 128;

    k_zero<<<(zmax + T - 1) / T, T>>>();
    k_count<<<(EE + T - 1) / T, T>>>(dst);
    k_dinv<<<(NN + T - 1) / T, T>>>();
    k_scan_part<<<NB, SCB>>>();
    k_scan_bsum<<<1, 256>>>();
    k_scan_add<<<(NN + T - 1) / T, T>>>();
    k_fill<<<(EE + T - 1) / T, T>>>(src, dst);

    k_fold<<<1, 512>>>(Wc, We);
    k_gemm16<<<NN / 32, T>>>(x);
    k_gather<<<(NN * 32 + T - 1) / T, T>>>();

    for (int l = 1; l < LL; l++) {
        k_gemm<<<GB, T>>>(Wc + (size_t)l * DD * DD);
        k_gather<<<(NN * 32 + T - 1) / T, T>>>();
    }

    k_cnt<<<(NN + T - 1) / T, T>>>(batch);
    k_distpool<<<GB, T>>>(cent, batch);

    k_out<<<(GG * KK + T - 1) / T, T>>>(Wout, bout, out);
}

// round 11
// speedup vs baseline: 5.6129x; 1.3075x over previous
#include <cuda_runtime.h>
#include <cuda_bf16.h>
#include <cstdint>
#include <math.h>

typedef unsigned int u32;

#define NN 100000
#define EE 1600000
#define GG 1000
#define FF 16
#define DD 128
#define CC 100
#define KK 2
#define LL 3

#define SCB 512
#define NB  ((NN + SCB - 1) / SCB)
#define KC 32
#define PAD 36

// ---------------- scratch ----------------
__device__ float g_dinv[NN];
__device__ float g_h[(size_t)NN * DD];
__device__ u32   g_mb[(size_t)NN * 64];   // messages, packed bf16x2 (64 words = 128 bf16 per row)
__device__ float g_pool[GG * CC];
__device__ float g_cnt[GG];
__device__ float g_wf[DD * FF];           // folded W1 @ W_embed
__device__ int   g_cnti[NN];
__device__ int   g_rowptr[NN + 1];
__device__ int   g_cursor[NN];
__device__ int   g_bsum[NB];
__device__ int   g_csr[EE];

__device__ __forceinline__ float2 bf2f(u32 u) {
    __nv_bfloat162 b = *(__nv_bfloat162*)&u;
    return __bfloat1622float2(b);
}
__device__ __forceinline__ u32 f2tf32(float f) {
    u32 r;
    asm("cvt.rna.tf32.f32 %0, %1;" : "=r"(r) : "f"(f));
    return r;
}
__device__ __forceinline__ void mma_tf32(float* d, u32 a0, u32 a1, u32 a2, u32 a3,
                                         u32 b0, u32 b1) {
    asm("mma.sync.aligned.m16n8k8.row.col.f32.tf32.tf32.f32 "
        "{%0,%1,%2,%3}, {%4,%5,%6,%7}, {%8,%9}, {%0,%1,%2,%3};"
        : "+f"(d[0]), "+f"(d[1]), "+f"(d[2]), "+f"(d[3])
        : "r"(a0), "r"(a1), "r"(a2), "r"(a3), "r"(b0), "r"(b1));
}

// ---------------- zero ----------------
__global__ void k_zero() {
    int i = blockIdx.x * blockDim.x + threadIdx.x;
    if (i < NN) g_cnti[i] = 0;
    if (i < GG * CC) g_pool[i] = 0.f;
    if (i < GG) g_cnt[i] = 0.f;
}

// ---------------- CSR build ----------------
__global__ void k_count(const int* __restrict__ dst) {
    int e = blockIdx.x * blockDim.x + threadIdx.x;
    if (e < EE) atomicAdd(&g_cnti[dst[e]], 1);
}
__global__ void k_dinv() {
    int i = blockIdx.x * blockDim.x + threadIdx.x;
    if (i < NN) g_dinv[i] = rsqrtf((float)(g_cnti[i] + 1));
}
__global__ void k_scan_part() {
    __shared__ int s[SCB];
    int t = threadIdx.x;
    int i = blockIdx.x * SCB + t;
    int v = (i < NN) ? g_cnti[i] : 0;
    s[t] = v;
    __syncthreads();
#pragma unroll
    for (int off = 1; off < SCB; off <<= 1) {
        int x = (t >= off) ? s[t - off] : 0;
        __syncthreads();
        s[t] += x;
        __syncthreads();
    }
    if (i < NN) g_rowptr[i] = s[t] - v;
    if (t == SCB - 1) g_bsum[blockIdx.x] = s[t];
}
__global__ void k_scan_bsum() {
    __shared__ int s[256];
    int t = threadIdx.x;
    int v = (t < NB) ? g_bsum[t] : 0;
    s[t] = v;
    __syncthreads();
#pragma unroll
    for (int off = 1; off < 256; off <<= 1) {
        int x = (t >= off) ? s[t - off] : 0;
        __syncthreads();
        s[t] += x;
        __syncthreads();
    }
    if (t < NB) g_bsum[t] = s[t] - v;
}
__global__ void k_scan_add() {
    int i = blockIdx.x * blockDim.x + threadIdx.x;
    if (i < NN) {
        int r = g_rowptr[i] + g_bsum[i / SCB];
        g_rowptr[i] = r;
        g_cursor[i] = r;
    }
    if (i == 0) g_rowptr[NN] = EE;
}
__global__ void k_fill(const int* __restrict__ src, const int* __restrict__ dst) {
    int e = blockIdx.x * blockDim.x + threadIdx.x;
    if (e < EE) {
        int d = dst[e];
        int pos = atomicAdd(&g_cursor[d], 1);
        g_csr[pos] = src[e];
    }
}

// ---------------- fold: Wf = W1 @ We ----------------
__global__ void k_fold(const float* __restrict__ W1, const float* __restrict__ We) {
    __shared__ float we[DD * FF];
    int tid = threadIdx.x;
    for (int i = tid; i < DD * FF; i += 512) we[i] = We[i];
    __syncthreads();
    for (int i = tid; i < DD * FF; i += 512) {
        int d = i >> 4, f = i & 15;
        float s = 0.f;
#pragma unroll 8
        for (int k = 0; k < DD; k++) s += W1[d * DD + k] * we[k * FF + f];
        g_wf[i] = s;
    }
}

// ---------------- layer0 transform: m = dinv * (x @ Wf^T), bf16 packed out ----------------
__global__ void k_gemm16(const float* __restrict__ x) {
    __shared__ float wt[FF * DD];   // wt[f*128 + d]
    __shared__ float xs[32 * FF];
    int tid = threadIdx.x;
    for (int idx = tid; idx < DD * FF; idx += 256) {
        int d = idx >> 4, f = idx & 15;
        wt[f * DD + d] = g_wf[idx];
    }
    int n0 = blockIdx.x * 32;
    for (int idx = tid; idx < 32 * FF; idx += 256) xs[idx] = x[(size_t)n0 * FF + idx];
    __syncthreads();

    int p = tid & 63;          // bf16x2 pair index: cols 2p, 2p+1
    int nb = tid >> 6;         // 4 nodes per pass
    int d0 = 2 * p;
#pragma unroll
    for (int it = 0; it < 8; it++) {
        int n = it * 4 + nb;
        float s0 = 0.f, s1 = 0.f;
#pragma unroll
        for (int f = 0; f < FF; f++) {
            float xv = xs[n * FF + f];
            s0 = fmaf(xv, wt[f * DD + d0], s0);
            s1 = fmaf(xv, wt[f * DD + d0 + 1], s1);
        }
        float sc = g_dinv[n0 + n];
        __nv_bfloat162 pk = __floats2bfloat162_rn(s0 * sc, s1 * sc);
        g_mb[(size_t)(n0 + n) * 64 + p] = *(u32*)&pk;
    }
}

// ---------------- GCN transform (tensor cores, tf32): m = dinv * (h @ W^T), bf16 out ----------------
__global__ void __launch_bounds__(256, 2) k_gemm_tc(const float* __restrict__ W) {
    __shared__ u32 Ws[DD][PAD];   // tf32 bits, Ws[dout][kk]
    __shared__ u32 hs[DD][PAD];   // tf32 bits, hs[row][kk]
    int tid = threadIdx.x;
    int warp = tid >> 5, lane = tid & 31;
    int lq = lane >> 2, lr = lane & 3;
    int n0 = blockIdx.x * 128;
    int wr = warp * 16;

    float acc[16][4];
#pragma unroll
    for (int t = 0; t < 16; t++)
#pragma unroll
        for (int q = 0; q < 4; q++) acc[t][q] = 0.f;

    for (int kc = 0; kc < DD; kc += KC) {
        for (int idx = tid; idx < DD * KC; idx += 256) {
            int r = idx >> 5, kk = idx & 31;
            Ws[r][kk] = f2tf32(W[r * DD + kc + kk]);
            int n = n0 + r;
            hs[r][kk] = f2tf32((n < NN) ? g_h[(size_t)n * DD + kc + kk] : 0.f);
        }
        __syncthreads();
#pragma unroll
        for (int kq = 0; kq < 4; kq++) {
            u32 a0 = hs[wr + lq][kq * 8 + lr];
            u32 a1 = hs[wr + lq + 8][kq * 8 + lr];
            u32 a2 = hs[wr + lq][kq * 8 + lr + 4];
            u32 a3 = hs[wr + lq + 8][kq * 8 + lr + 4];
#pragma unroll
            for (int t = 0; t < 16; t++) {
                u32 b0 = Ws[t * 8 + lq][kq * 8 + lr];
                u32 b1 = Ws[t * 8 + lq][kq * 8 + lr + 4];
                mma_tf32(acc[t], a0, a1, a2, a3, b0, b1);
            }
        }
        __syncthreads();
    }

    // D frag: c0,c1 = (row wr+lq, cols 8t+2lr, +1); c2,c3 = (row wr+lq+8, same cols)
    int r0 = n0 + wr + lq, r1 = r0 + 8;
    float s0 = (r0 < NN) ? g_dinv[r0] : 0.f;
    float s1 = (r1 < NN) ? g_dinv[r1] : 0.f;
#pragma unroll
    for (int t = 0; t < 16; t++) {
        if (r0 < NN) {
            __nv_bfloat162 p = __floats2bfloat162_rn(acc[t][0] * s0, acc[t][1] * s0);
            g_mb[(size_t)r0 * 64 + t * 4 + lr] = *(u32*)&p;
        }
        if (r1 < NN) {
            __nv_bfloat162 p = __floats2bfloat162_rn(acc[t][2] * s1, acc[t][3] * s1);
            g_mb[(size_t)r1 * 64 + t * 4 + lr] = *(u32*)&p;
        }
    }
}

// ---------------- gather: h[v] = relu(dinv[v] * (m[v] + sum m[u])), bf16 in / fp32 out ----------------
__global__ void k_gather() {
    int w = (blockIdx.x * 256 + threadIdx.x) >> 5;
    int lane = threadIdx.x & 31;
    if (w >= NN) return;
    int beg = g_rowptr[w], end = g_rowptr[w + 1];
    const uint2* M2 = (const uint2*)g_mb;     // row = 32 uint2; lane covers cols 4l..4l+3

    uint2 sr = M2[(size_t)w * 32 + lane];
    float2 sa = bf2f(sr.x), sb = bf2f(sr.y);
    float4 acc = make_float4(sa.x, sa.y, sb.x, sb.y);
    float4 acc2 = make_float4(0.f, 0.f, 0.f, 0.f);

    int i = beg;
    int cnt = end - beg;
    while (cnt > 0) {
        int take = cnt > 32 ? 32 : cnt;
        int nb = (lane < take) ? g_csr[i + lane] : 0;
        int j = 0;
        for (; j + 8 <= take; j += 8) {
            int u0 = __shfl_sync(0xffffffffu, nb, j);
            int u1 = __shfl_sync(0xffffffffu, nb, j + 1);
            int u2 = __shfl_sync(0xffffffffu, nb, j + 2);
            int u3 = __shfl_sync(0xffffffffu, nb, j + 3);
            int u4 = __shfl_sync(0xffffffffu, nb, j + 4);
            int u5 = __shfl_sync(0xffffffffu, nb, j + 5);
            int u6 = __shfl_sync(0xffffffffu, nb, j + 6);
            int u7 = __shfl_sync(0xffffffffu, nb, j + 7);
            uint2 r0 = M2[(size_t)u0 * 32 + lane];
            uint2 r1 = M2[(size_t)u1 * 32 + lane];
            uint2 r2 = M2[(size_t)u2 * 32 + lane];
            uint2 r3 = M2[(size_t)u3 * 32 + lane];
            uint2 r4 = M2[(size_t)u4 * 32 + lane];
            uint2 r5 = M2[(size_t)u5 * 32 + lane];
            uint2 r6 = M2[(size_t)u6 * 32 + lane];
            uint2 r7 = M2[(size_t)u7 * 32 + lane];
            float2 a0 = bf2f(r0.x), b0 = bf2f(r0.y);
            float2 a1 = bf2f(r1.x), b1 = bf2f(r1.y);
            float2 a2 = bf2f(r2.x), b2 = bf2f(r2.y);
            float2 a3 = bf2f(r3.x), b3 = bf2f(r3.y);
            float2 a4 = bf2f(r4.x), b4 = bf2f(r4.y);
            float2 a5 = bf2f(r5.x), b5 = bf2f(r5.y);
            float2 a6 = bf2f(r6.x), b6 = bf2f(r6.y);
            float2 a7 = bf2f(r7.x), b7 = bf2f(r7.y);
            acc.x += (a0.x + a1.x) + (a2.x + a3.x);
            acc.y += (a0.y + a1.y) + (a2.y + a3.y);
            acc.z += (b0.x + b1.x) + (b2.x + b3.x);
            acc.w += (b0.y + b1.y) + (b2.y + b3.y);
            acc2.x += (a4.x + a5.x) + (a6.x + a7.x);
            acc2.y += (a4.y + a5.y) + (a6.y + a7.y);
            acc2.z += (b4.x + b5.x) + (b6.x + b7.x);
            acc2.w += (b4.y + b5.y) + (b6.y + b7.y);
        }
        for (; j < take; j++) {
            int u = __shfl_sync(0xffffffffu, nb, j);
            uint2 r = M2[(size_t)u * 32 + lane];
            float2 a = bf2f(r.x), b = bf2f(r.y);
            acc2.x += a.x; acc2.y += a.y; acc2.z += b.x; acc2.w += b.y;
        }
        i += take;
        cnt -= take;
    }
    acc.x += acc2.x; acc.y += acc2.y; acc.z += acc2.z; acc.w += acc2.w;

    float sc = g_dinv[w];
    acc.x = fmaxf(acc.x * sc, 0.f);
    acc.y = fmaxf(acc.y * sc, 0.f);
    acc.z = fmaxf(acc.z * sc, 0.f);
    acc.w = fmaxf(acc.w * sc, 0.f);
    ((float4*)g_h)[(size_t)w * 32 + lane] = acc;
}

// ---------------- batch counts ----------------
__global__ void k_cnt(const int* __restrict__ batch) {
    int i = blockIdx.x * blockDim.x + threadIdx.x;
    if (i < NN) atomicAdd(&g_cnt[batch[i]], 1.0f);
}

// ---------------- distances + pool (tensor cores): d2 = x2 + c2 - 2 h.c ----------------
// dynamic smem layout:
//   phase 1: cs[128][36] u32 | hs[128][36] u32           (36.9 KB, at offset 0)
//   phase 2: dist[128][132] float                        (67.6 KB, overlays phase 1)
//   always:  sx2[128] | sc2[128] | sg[128]               (after dist region)
#define DP_SMEM (DD * 132 * 4 + 3 * DD * 4)
__global__ void __launch_bounds__(256, 2) k_distpool_tc(const float* __restrict__ cent,
                                                        const int* __restrict__ batch) {
    extern __shared__ float dsm[];
    u32* cs = (u32*)dsm;                   // [128][36]
    u32* hs = cs + DD * PAD;               // [128][36]
    float* dist = dsm;                     // [128][132] (phase 2)
    float* sx2 = dsm + DD * 132;
    float* sc2 = sx2 + DD;
    int*   sg  = (int*)(sc2 + DD);

    int tid = threadIdx.x;
    int warp = tid >> 5, lane = tid & 31;
    int lq = lane >> 2, lr = lane & 3;
    int n0 = blockIdx.x * 128;
    int wr = warp * 16;

    if (tid < DD) {
        sx2[tid] = 0.f;
        sc2[tid] = 0.f;
        int n = n0 + tid;
        sg[tid] = (n < NN) ? batch[n] : -1;
    }

    float acc[16][4];
#pragma unroll
    for (int t = 0; t < 16; t++)
#pragma unroll
        for (int q = 0; q < 4; q++) acc[t][q] = 0.f;

    for (int kc = 0; kc < DD; kc += KC) {
        for (int idx = tid; idx < DD * KC; idx += 256) {
            int r = idx >> 5, kk = idx & 31;
            cs[r * PAD + kk] = f2tf32((r < CC) ? cent[r * DD + kc + kk] : 0.f);
            int n = n0 + r;
            hs[r * PAD + kk] = f2tf32((n < NN) ? g_h[(size_t)n * DD + kc + kk] : 0.f);
        }
        __syncthreads();
#pragma unroll
        for (int kq = 0; kq < 4; kq++) {
            u32 a0 = hs[(wr + lq) * PAD + kq * 8 + lr];
            u32 a1 = hs[(wr + lq + 8) * PAD + kq * 8 + lr];
            u32 a2 = hs[(wr + lq) * PAD + kq * 8 + lr + 4];
            u32 a3 = hs[(wr + lq + 8) * PAD + kq * 8 + lr + 4];
#pragma unroll
            for (int t = 0; t < 16; t++) {
                u32 b0 = cs[(t * 8 + lq) * PAD + kq * 8 + lr];
                u32 b1 = cs[(t * 8 + lq) * PAD + kq * 8 + lr + 4];
                mma_tf32(acc[t], a0, a1, a2, a3, b0, b1);
            }
        }
        // norms from the tf32-truncated values (consistent with the mma products)
        if (tid < DD) {
            float sh = 0.f, sc = 0.f;
#pragma unroll 8
            for (int kk = 0; kk < KC; kk++) {
                float hv = __uint_as_float(hs[tid * PAD + kk]);
                float cv = __uint_as_float(cs[tid * PAD + kk]);
                sh = fmaf(hv, hv, sh);
                sc = fmaf(cv, cv, sc);
            }
            sx2[tid] += sh;
            sc2[tid] += sc;
        }
        __syncthreads();
    }

    // phase 2: write dist (overlays cs/hs — all reads completed at last sync)
    int R0 = wr + lq, R1 = R0 + 8;
    float x0 = sx2[R0], x1 = sx2[R1];
#pragma unroll
    for (int t = 0; t < 16; t++) {
        int c = t * 8 + 2 * lr;
        float c2a = sc2[c], c2b = sc2[c + 1];
        float d0 = sqrtf(fmaxf(x0 + c2a - 2.f * acc[t][0], 0.f) + 1e-12f);
        float d1 = sqrtf(fmaxf(x0 + c2b - 2.f * acc[t][1], 0.f) + 1e-12f);
        float d2 = sqrtf(fmaxf(x1 + c2a - 2.f * acc[t][2], 0.f) + 1e-12f);
        float d3 = sqrtf(fmaxf(x1 + c2b - 2.f * acc[t][3], 0.f) + 1e-12f);
        *(float2*)&dist[R0 * 132 + c] = make_float2(d0, d1);
        *(float2*)&dist[R1 * 132 + c] = make_float2(d2, d3);
    }
    __syncthreads();

    // pooling: 2 threads per column, run-aggregated by graph (batch sorted)
    int c = tid & 127, half = tid >> 7;
    if (c < CC) {
        int rbeg = half * 64, rend = rbeg + 64;
        int cur = -2;
        float s = 0.f;
        for (int r = rbeg; r < rend; r++) {
            int g = sg[r];
            if (g < 0) break;     // invalid rows only at the tail (batch sorted)
            float v = dist[r * 132 + c];
            if (g == cur) s += v;
            else {
                if (cur >= 0) atomicAdd(&g_pool[cur * CC + c], s);
                cur = g; s = v;
            }
        }
        if (cur >= 0) atomicAdd(&g_pool[cur * CC + c], s);
    }
}

// ---------------- output ----------------
__global__ void k_out(const float* __restrict__ Wout, const float* __restrict__ bout,
                      float* __restrict__ out) {
    int i = blockIdx.x * blockDim.x + threadIdx.x;
    if (i < GG * KK) {
        int g = i / KK, k = i % KK;
        float inv = 1.0f / fmaxf(g_cnt[g], 1.0f);
        float s = 0.f;
#pragma unroll 4
        for (int c = 0; c < CC; c++) s += g_pool[g * CC + c] * Wout[k * CC + c];
        out[i] = s * inv + bout[k];
    }
}

extern "C" void kernel_launch(void* const* d_in, const int* in_sizes, int n_in,
                              void* d_out, int out_size) {
    const float* x     = (const float*)d_in[0];
    const int*   ei    = (const int*)d_in[1];
    const int*   batch = (const int*)d_in[2];
    const float* We    = (const float*)d_in[3];
    const float* Wc    = (const float*)d_in[4];
    const float* cent  = (const float*)d_in[5];
    const float* Wout  = (const float*)d_in[6];
    const float* bout  = (const float*)d_in[7];
    float* out = (float*)d_out;

    const int* src = ei;
    const int* dst = ei + EE;

    cudaFuncSetAttribute(k_distpool_tc, cudaFuncAttributeMaxDynamicSharedMemorySize, DP_SMEM);

    const int T = 256;
    int zmax = (NN > GG * CC) ? NN : GG * CC;
    const int GB = (NN + 127) / 128;

    k_zero<<<(zmax + T - 1) / T, T>>>();
    k_count<<<(EE + T - 1) / T, T>>>(dst);
    k_dinv<<<(NN + T - 1) / T, T>>>();
    k_scan_part<<<NB, SCB>>>();
    k_scan_bsum<<<1, 256>>>();
    k_scan_add<<<(NN + T - 1) / T, T>>>();
    k_fill<<<(EE + T - 1) / T, T>>>(src, dst);

    k_fold<<<1, 512>>>(Wc, We);
    k_gemm16<<<NN / 32, T>>>(x);
    k_gather<<<(NN * 32 + T - 1) / T, T>>>();

    for (int l = 1; l < LL; l++) {
        k_gemm_tc<<<GB, T>>>(Wc + (size_t)l * DD * DD);
        k_gather<<<(NN * 32 + T - 1) / T, T>>>();
    }

    k_cnt<<<(NN + T - 1) / T, T>>>(batch);
    k_distpool_tc<<<GB, T, DP_SMEM>>>(cent, batch);

    k_out<<<(GG * KK + T - 1) / T, T>>>(Wout, bout, out);
}

// round 14
// speedup vs baseline: 5.6639x; 1.0091x over previous
#include <cuda_runtime.h>
#include <cuda_bf16.h>
#include <cstdint>
#include <math.h>

typedef unsigned int u32;

#define NN 100000
#define EE 1600000
#define GG 1000
#define FF 16
#define DD 128
#define CC 100
#define KK 2
#define LL 3

#define SCB 512
#define NB  ((NN + SCB - 1) / SCB)
#define KC 32
#define PAD 36

// ---------------- scratch ----------------
__device__ float g_dinv[NN];
__device__ float g_h[(size_t)NN * DD];
__device__ u32   g_mb[(size_t)NN * 64];   // messages, packed bf16x2 (64 words = 128 bf16 per row)
__device__ float g_pool[GG * CC];
__device__ float g_cnt[GG];
__device__ float g_wf[DD * FF];           // folded W1 @ W_embed
__device__ int   g_cnti[NN];
__device__ int   g_rowptr[NN + 1];
__device__ int   g_cursor[NN];
__device__ int   g_bsum[NB];
__device__ int   g_csr[EE];

__device__ __forceinline__ float2 bf2f(u32 u) {
    __nv_bfloat162 b = *(__nv_bfloat162*)&u;
    return __bfloat1622float2(b);
}
__device__ __forceinline__ u32 f2tf32(float f) {
    u32 r;
    asm("cvt.rna.tf32.f32 %0, %1;" : "=r"(r) : "f"(f));
    return r;
}
__device__ __forceinline__ void mma_tf32(float* d, u32 a0, u32 a1, u32 a2, u32 a3,
                                         u32 b0, u32 b1) {
    asm("mma.sync.aligned.m16n8k8.row.col.f32.tf32.tf32.f32 "
        "{%0,%1,%2,%3}, {%4,%5,%6,%7}, {%8,%9}, {%0,%1,%2,%3};"
        : "+f"(d[0]), "+f"(d[1]), "+f"(d[2]), "+f"(d[3])
        : "r"(a0), "r"(a1), "r"(a2), "r"(a3), "r"(b0), "r"(b1));
}

// ---------------- zero ----------------
__global__ void k_zero() {
    int i = blockIdx.x * blockDim.x + threadIdx.x;
    if (i < NN) g_cnti[i] = 0;
    if (i < GG * CC) g_pool[i] = 0.f;
    if (i < GG) g_cnt[i] = 0.f;
}

// ---------------- CSR build (+ batch counts fused) ----------------
__global__ void k_count(const int* __restrict__ dst, const int* __restrict__ batch) {
    int e = blockIdx.x * blockDim.x + threadIdx.x;
    if (e < EE) atomicAdd(&g_cnti[dst[e]], 1);
    if (e < NN) atomicAdd(&g_cnt[batch[e]], 1.0f);
}
__global__ void k_scan_part() {
    __shared__ int s[SCB];
    int t = threadIdx.x;
    int i = blockIdx.x * SCB + t;
    int v = (i < NN) ? g_cnti[i] : 0;
    s[t] = v;
    __syncthreads();
#pragma unroll
    for (int off = 1; off < SCB; off <<= 1) {
        int x = (t >= off) ? s[t - off] : 0;
        __syncthreads();
        s[t] += x;
        __syncthreads();
    }
    if (i < NN) g_rowptr[i] = s[t] - v;
    if (t == SCB - 1) g_bsum[blockIdx.x] = s[t];
}
__global__ void k_scan_bsum() {
    __shared__ int s[256];
    int t = threadIdx.x;
    int v = (t < NB) ? g_bsum[t] : 0;
    s[t] = v;
    __syncthreads();
#pragma unroll
    for (int off = 1; off < 256; off <<= 1) {
        int x = (t >= off) ? s[t - off] : 0;
        __syncthreads();
        s[t] += x;
        __syncthreads();
    }
    if (t < NB) g_bsum[t] = s[t] - v;
}
__global__ void k_scan_add() {
    int i = blockIdx.x * blockDim.x + threadIdx.x;
    if (i < NN) {
        int r = g_rowptr[i] + g_bsum[i / SCB];
        g_rowptr[i] = r;
        g_cursor[i] = r;
        g_dinv[i] = rsqrtf((float)(g_cnti[i] + 1));   // fused dinv
    }
    if (i == 0) g_rowptr[NN] = EE;
}
__global__ void k_fill(const int* __restrict__ src, const int* __restrict__ dst) {
    int e = blockIdx.x * blockDim.x + threadIdx.x;
    if (e < EE) {
        int d = dst[e];
        int pos = atomicAdd(&g_cursor[d], 1);
        g_csr[pos] = src[e];
    }
}

// ---------------- fold: Wf = W1 @ We ----------------
__global__ void k_fold(const float* __restrict__ W1, const float* __restrict__ We) {
    __shared__ float we[DD * FF];
    int tid = threadIdx.x;
    for (int i = tid; i < DD * FF; i += 512) we[i] = We[i];
    __syncthreads();
    for (int i = tid; i < DD * FF; i += 512) {
        int d = i >> 4, f = i & 15;
        float s = 0.f;
#pragma unroll 8
        for (int k = 0; k < DD; k++) s += W1[d * DD + k] * we[k * FF + f];
        g_wf[i] = s;
    }
}

// ---------------- layer0 transform: m = dinv * (x @ Wf^T), bf16 packed out ----------------
__global__ void k_gemm16(const float* __restrict__ x) {
    __shared__ float wt[FF * DD];   // wt[f*128 + d]
    __shared__ float xs[32 * FF];
    int tid = threadIdx.x;
    for (int idx = tid; idx < DD * FF; idx += 256) {
        int d = idx >> 4, f = idx & 15;
        wt[f * DD + d] = g_wf[idx];
    }
    int n0 = blockIdx.x * 32;
    for (int idx = tid; idx < 32 * FF; idx += 256) xs[idx] = x[(size_t)n0 * FF + idx];
    __syncthreads();

    int p = tid & 63;          // bf16x2 pair index: cols 2p, 2p+1
    int nb = tid >> 6;         // 4 nodes per pass
    int d0 = 2 * p;
#pragma unroll
    for (int it = 0; it < 8; it++) {
        int n = it * 4 + nb;
        float s0 = 0.f, s1 = 0.f;
#pragma unroll
        for (int f = 0; f < FF; f++) {
            float xv = xs[n * FF + f];
            s0 = fmaf(xv, wt[f * DD + d0], s0);
            s1 = fmaf(xv, wt[f * DD + d0 + 1], s1);
        }
        float sc = g_dinv[n0 + n];
        __nv_bfloat162 pk = __floats2bfloat162_rn(s0 * sc, s1 * sc);
        g_mb[(size_t)(n0 + n) * 64 + p] = *(u32*)&pk;
    }
}

// ---------------- GCN transform (tensor cores, tf32): m = dinv * (h @ W^T), bf16 out ----------------
__global__ void __launch_bounds__(256, 2) k_gemm_tc(const float* __restrict__ W) {
    __shared__ u32 Ws[DD][PAD];   // tf32 bits, Ws[dout][kk]
    __shared__ u32 hs[DD][PAD];   // tf32 bits, hs[row][kk]
    int tid = threadIdx.x;
    int warp = tid >> 5, lane = tid & 31;
    int lq = lane >> 2, lr = lane & 3;
    int n0 = blockIdx.x * 128;
    int wr = warp * 16;

    float acc[16][4];
#pragma unroll
    for (int t = 0; t < 16; t++)
#pragma unroll
        for (int q = 0; q < 4; q++) acc[t][q] = 0.f;

    for (int kc = 0; kc < DD; kc += KC) {
        for (int idx = tid; idx < DD * KC; idx += 256) {
            int r = idx >> 5, kk = idx & 31;
            Ws[r][kk] = f2tf32(W[r * DD + kc + kk]);
            int n = n0 + r;
            hs[r][kk] = f2tf32((n < NN) ? g_h[(size_t)n * DD + kc + kk] : 0.f);
        }
        __syncthreads();
#pragma unroll
        for (int kq = 0; kq < 4; kq++) {
            u32 a0 = hs[wr + lq][kq * 8 + lr];
            u32 a1 = hs[wr + lq + 8][kq * 8 + lr];
            u32 a2 = hs[wr + lq][kq * 8 + lr + 4];
            u32 a3 = hs[wr + lq + 8][kq * 8 + lr + 4];
#pragma unroll
            for (int t = 0; t < 16; t++) {
                u32 b0 = Ws[t * 8 + lq][kq * 8 + lr];
                u32 b1 = Ws[t * 8 + lq][kq * 8 + lr + 4];
                mma_tf32(acc[t], a0, a1, a2, a3, b0, b1);
            }
        }
        __syncthreads();
    }

    int r0 = n0 + wr + lq, r1 = r0 + 8;
    float s0 = (r0 < NN) ? g_dinv[r0] : 0.f;
    float s1 = (r1 < NN) ? g_dinv[r1] : 0.f;
#pragma unroll
    for (int t = 0; t < 16; t++) {
        if (r0 < NN) {
            __nv_bfloat162 p = __floats2bfloat162_rn(acc[t][0] * s0, acc[t][1] * s0);
            g_mb[(size_t)r0 * 64 + t * 4 + lr] = *(u32*)&p;
        }
        if (r1 < NN) {
            __nv_bfloat162 p = __floats2bfloat162_rn(acc[t][2] * s1, acc[t][3] * s1);
            g_mb[(size_t)r1 * 64 + t * 4 + lr] = *(u32*)&p;
        }
    }
}

// ---------------- gather: warp per node, 2 edges in flight (half-warp each), full-warp shfl ----------------
#define ACC8(r) { \
    float2 q0 = bf2f((r).x), q1 = bf2f((r).y), q2 = bf2f((r).z), q3 = bf2f((r).w); \
    a0 += q0.x; a1 += q0.y; a2 += q1.x; a3 += q1.y; \
    a4 += q2.x; a5 += q2.y; a6 += q3.x; a7 += q3.y; }

__global__ void k_gather() {
    int w = (blockIdx.x * 256 + threadIdx.x) >> 5;
    int lane = threadIdx.x & 31;
    int half = lane >> 4, l16 = lane & 15;
    if (w >= NN) return;
    const uint4* M4 = (const uint4*)g_mb;   // row = 16 uint4 (256 B); lane covers slot l16 of edge j+half

    float a0 = 0.f, a1 = 0.f, a2 = 0.f, a3 = 0.f;
    float a4 = 0.f, a5 = 0.f, a6 = 0.f, a7 = 0.f;
    if (half == 0) {                         // self loop counted once
        uint4 sr = M4[(size_t)w * 16 + l16];
        ACC8(sr)
    }

    int i = g_rowptr[w];
    int cnt = g_rowptr[w + 1] - i;
    while (cnt > 0) {
        int take = cnt > 32 ? 32 : cnt;
        int nb = (lane < take) ? g_csr[i + lane] : 0;
        int j = 0;
        // main: 8 edges per iteration, 4 unconditional uint4 loads per lane
        for (; j + 8 <= take; j += 8) {
            int u0 = __shfl_sync(0xffffffffu, nb, j + half);
            int u1 = __shfl_sync(0xffffffffu, nb, j + 2 + half);
            int u2 = __shfl_sync(0xffffffffu, nb, j + 4 + half);
            int u3 = __shfl_sync(0xffffffffu, nb, j + 6 + half);
            uint4 r0 = M4[(size_t)u0 * 16 + l16];
            uint4 r1 = M4[(size_t)u1 * 16 + l16];
            uint4 r2 = M4[(size_t)u2 * 16 + l16];
            uint4 r3 = M4[(size_t)u3 * 16 + l16];
            ACC8(r0) ACC8(r1) ACC8(r2) ACC8(r3)
        }
        // tail: 2 edges per step, load predicated (shfl index always < 32)
        for (; j < take; j += 2) {
            int jj = j + half;
            int u = __shfl_sync(0xffffffffu, nb, jj < 31 ? jj : 31);
            if (jj < take) {
                uint4 r = M4[(size_t)u * 16 + l16];
                ACC8(r)
            }
        }
        i += take;
        cnt -= take;
    }

    // combine the two edge-halves
    a0 += __shfl_xor_sync(0xffffffffu, a0, 16);
    a1 += __shfl_xor_sync(0xffffffffu, a1, 16);
    a2 += __shfl_xor_sync(0xffffffffu, a2, 16);
    a3 += __shfl_xor_sync(0xffffffffu, a3, 16);
    a4 += __shfl_xor_sync(0xffffffffu, a4, 16);
    a5 += __shfl_xor_sync(0xffffffffu, a5, 16);
    a6 += __shfl_xor_sync(0xffffffffu, a6, 16);
    a7 += __shfl_xor_sync(0xffffffffu, a7, 16);

    if (half == 0) {
        float sc = g_dinv[w];
        float4 o0 = make_float4(fmaxf(a0 * sc, 0.f), fmaxf(a1 * sc, 0.f),
                                fmaxf(a2 * sc, 0.f), fmaxf(a3 * sc, 0.f));
        float4 o1 = make_float4(fmaxf(a4 * sc, 0.f), fmaxf(a5 * sc, 0.f),
                                fmaxf(a6 * sc, 0.f), fmaxf(a7 * sc, 0.f));
        float4* H = (float4*)g_h;
        H[(size_t)w * 32 + l16 * 2] = o0;
        H[(size_t)w * 32 + l16 * 2 + 1] = o1;
    }
}

// ---------------- distances + pool (tensor cores): d2 = x2 + c2 - 2 h.c ----------------
#define DP_SMEM (DD * 132 * 4 + 3 * DD * 4)
__global__ void __launch_bounds__(256, 2) k_distpool_tc(const float* __restrict__ cent,
                                                        const int* __restrict__ batch) {
    extern __shared__ float dsm[];
    u32* cs = (u32*)dsm;                   // [128][36]
    u32* hs = cs + DD * PAD;               // [128][36]
    float* dist = dsm;                     // [128][132] (phase 2)
    float* sx2 = dsm + DD * 132;
    float* sc2 = sx2 + DD;
    int*   sg  = (int*)(sc2 + DD);

    int tid = threadIdx.x;
    int warp = tid >> 5, lane = tid & 31;
    int lq = lane >> 2, lr = lane & 3;
    int n0 = blockIdx.x * 128;
    int wr = warp * 16;

    if (tid < DD) {
        sx2[tid] = 0.f;
        sc2[tid] = 0.f;
        int n = n0 + tid;
        sg[tid] = (n < NN) ? batch[n] : -1;
    }

    float acc[16][4];
#pragma unroll
    for (int t = 0; t < 16; t++)
#pragma unroll
        for (int q = 0; q < 4; q++) acc[t][q] = 0.f;

    for (int kc = 0; kc < DD; kc += KC) {
        for (int idx = tid; idx < DD * KC; idx += 256) {
            int r = idx >> 5, kk = idx & 31;
            cs[r * PAD + kk] = f2tf32((r < CC) ? cent[r * DD + kc + kk] : 0.f);
            int n = n0 + r;
            hs[r * PAD + kk] = f2tf32((n < NN) ? g_h[(size_t)n * DD + kc + kk] : 0.f);
        }
        __syncthreads();
#pragma unroll
        for (int kq = 0; kq < 4; kq++) {
            u32 a0 = hs[(wr + lq) * PAD + kq * 8 + lr];
            u32 a1 = hs[(wr + lq + 8) * PAD + kq * 8 + lr];
            u32 a2 = hs[(wr + lq) * PAD + kq * 8 + lr + 4];
            u32 a3 = hs[(wr + lq + 8) * PAD + kq * 8 + lr + 4];
#pragma unroll
            for (int t = 0; t < 16; t++) {
                u32 b0 = cs[(t * 8 + lq) * PAD + kq * 8 + lr];
                u32 b1 = cs[(t * 8 + lq) * PAD + kq * 8 + lr + 4];
                mma_tf32(acc[t], a0, a1, a2, a3, b0, b1);
            }
        }
        if (tid < DD) {
            float sh = 0.f, sc = 0.f;
#pragma unroll 8
            for (int kk = 0; kk < KC; kk++) {
                float hv = __uint_as_float(hs[tid * PAD + kk]);
                float cv = __uint_as_float(cs[tid * PAD + kk]);
                sh = fmaf(hv, hv, sh);
                sc = fmaf(cv, cv, sc);
            }
            sx2[tid] += sh;
            sc2[tid] += sc;
        }
        __syncthreads();
    }

    int R0 = wr + lq, R1 = R0 + 8;
    float x0 = sx2[R0], x1 = sx2[R1];
#pragma unroll
    for (int t = 0; t < 16; t++) {
        int c = t * 8 + 2 * lr;
        float c2a = sc2[c], c2b = sc2[c + 1];
        float d0 = sqrtf(fmaxf(x0 + c2a - 2.f * acc[t][0], 0.f) + 1e-12f);
        float d1 = sqrtf(fmaxf(x0 + c2b - 2.f * acc[t][1], 0.f) + 1e-12f);
        float d2 = sqrtf(fmaxf(x1 + c2a - 2.f * acc[t][2], 0.f) + 1e-12f);
        float d3 = sqrtf(fmaxf(x1 + c2b - 2.f * acc[t][3], 0.f) + 1e-12f);
        *(float2*)&dist[R0 * 132 + c] = make_float2(d0, d1);
        *(float2*)&dist[R1 * 132 + c] = make_float2(d2, d3);
    }
    __syncthreads();

    int c = tid & 127, half = tid >> 7;
    if (c < CC) {
        int rbeg = half * 64, rend = rbeg + 64;
        int cur = -2;
        float s = 0.f;
        for (int r = rbeg; r < rend; r++) {
            int g = sg[r];
            if (g < 0) break;
            float v = dist[r * 132 + c];
            if (g == cur) s += v;
            else {
                if (cur >= 0) atomicAdd(&g_pool[cur * CC + c], s);
                cur = g; s = v;
            }
        }
        if (cur >= 0) atomicAdd(&g_pool[cur * CC + c], s);
    }
}

// ---------------- output ----------------
__global__ void k_out(const float* __restrict__ Wout, const float* __restrict__ bout,
                      float* __restrict__ out) {
    int i = blockIdx.x * blockDim.x + threadIdx.x;
    if (i < GG * KK) {
        int g = i / KK, k = i % KK;
        float inv = 1.0f / fmaxf(g_cnt[g], 1.0f);
        float s = 0.f;
#pragma unroll 4
        for (int c = 0; c < CC; c++) s += g_pool[g * CC + c] * Wout[k * CC + c];
        out[i] = s * inv + bout[k];
    }
}

extern "C" void kernel_launch(void* const* d_in, const int* in_sizes, int n_in,
                              void* d_out, int out_size) {
    const float* x     = (const float*)d_in[0];
    const int*   ei    = (const int*)d_in[1];
    const int*   batch = (const int*)d_in[2];
    const float* We    = (const float*)d_in[3];
    const float* Wc    = (const float*)d_in[4];
    const float* cent  = (const float*)d_in[5];
    const float* Wout  = (const float*)d_in[6];
    const float* bout  = (const float*)d_in[7];
    float* out = (float*)d_out;

    const int* src = ei;
    const int* dst = ei + EE;

    cudaFuncSetAttribute(k_distpool_tc, cudaFuncAttributeMaxDynamicSharedMemorySize, DP_SMEM);

    const int T = 256;
    int zmax = (NN > GG * CC) ? NN : GG * CC;
    const int GB = (NN + 127) / 128;
    const int GATHB = (NN * 32 + T - 1) / T;

    k_zero<<<(zmax + T - 1) / T, T>>>();
    k_count<<<(EE + T - 1) / T, T>>>(dst, batch);
    k_scan_part<<<NB, SCB>>>();
    k_scan_bsum<<<1, 256>>>();
    k_scan_add<<<(NN + T - 1) / T, T>>>();
    k_fill<<<(EE + T - 1) / T, T>>>(src, dst);

    k_fold<<<1, 512>>>(Wc, We);
    k_gemm16<<<NN / 32, T>>>(x);
    k_gather<<<GATHB, T>>>();

    for (int l = 1; l < LL; l++) {
        k_gemm_tc<<<GB, T>>>(Wc + (size_t)l * DD * DD);
        k_gather<<<GATHB, T>>>();
    }

    k_distpool_tc<<<GB, T, DP_SMEM>>>(cent, batch);

    k_out<<<(GG * KK + T - 1) / T, T>>>(Wout, bout, out);
}

// round 15
// speedup vs baseline: 6.9570x; 1.2283x over previous
#include <cuda_runtime.h>
#include <cuda_bf16.h>
#include <cstdint>
#include <math.h>

typedef unsigned int u32;

#define NN 100000
#define EE 1600000
#define GG 1000
#define FF 16
#define DD 128
#define CC 100
#define KK 2
#define LL 3

#define SCB 512
#define NB  ((NN + SCB - 1) / SCB)
#define KC 64          // k-chunk (elements); 32 bf16x2 words per row per chunk
#define PAD 36         // word pitch (32 used) -> conflict-free fragment loads

// ---------------- scratch ----------------
__device__ float g_dinv[NN];
__device__ u32   g_hb[(size_t)NN * 64];   // h, packed bf16x2 (64 words = 128 bf16 per row)
__device__ u32   g_mb[(size_t)NN * 64];   // messages, packed bf16x2
__device__ float g_pool[GG * CC];
__device__ float g_cnt[GG];
__device__ float g_wf[DD * FF];           // folded W1 @ W_embed
__device__ int   g_cnti[NN];
__device__ int   g_rowptr[NN + 1];
__device__ int   g_cursor[NN];
__device__ int   g_bsum[NB];
__device__ int   g_csr[EE];

__device__ __forceinline__ float2 bf2f(u32 u) {
    __nv_bfloat162 b = *(__nv_bfloat162*)&u;
    return __bfloat1622float2(b);
}
__device__ __forceinline__ u32 f2bf2(float a, float b) {
    __nv_bfloat162 p = __floats2bfloat162_rn(a, b);
    return *(u32*)&p;
}
__device__ __forceinline__ void mma_bf16(float* d, u32 a0, u32 a1, u32 a2, u32 a3,
                                         u32 b0, u32 b1) {
    asm("mma.sync.aligned.m16n8k16.row.col.f32.bf16.bf16.f32 "
        "{%0,%1,%2,%3}, {%4,%5,%6,%7}, {%8,%9}, {%0,%1,%2,%3};"
        : "+f"(d[0]), "+f"(d[1]), "+f"(d[2]), "+f"(d[3])
        : "r"(a0), "r"(a1), "r"(a2), "r"(a3), "r"(b0), "r"(b1));
}

// ---------------- zero ----------------
__global__ void k_zero() {
    int i = blockIdx.x * blockDim.x + threadIdx.x;
    if (i < NN) g_cnti[i] = 0;
    if (i < GG * CC) g_pool[i] = 0.f;
    if (i < GG) g_cnt[i] = 0.f;
}

// ---------------- CSR build (+ batch counts fused) ----------------
__global__ void k_count(const int* __restrict__ dst, const int* __restrict__ batch) {
    int e = blockIdx.x * blockDim.x + threadIdx.x;
    if (e < EE) atomicAdd(&g_cnti[dst[e]], 1);
    if (e < NN) atomicAdd(&g_cnt[batch[e]], 1.0f);
}
__global__ void k_scan_part() {
    __shared__ int s[SCB];
    int t = threadIdx.x;
    int i = blockIdx.x * SCB + t;
    int v = (i < NN) ? g_cnti[i] : 0;
    s[t] = v;
    __syncthreads();
#pragma unroll
    for (int off = 1; off < SCB; off <<= 1) {
        int x = (t >= off) ? s[t - off] : 0;
        __syncthreads();
        s[t] += x;
        __syncthreads();
    }
    if (i < NN) g_rowptr[i] = s[t] - v;
    if (t == SCB - 1) g_bsum[blockIdx.x] = s[t];
}
__global__ void k_scan_bsum() {
    __shared__ int s[256];
    int t = threadIdx.x;
    int v = (t < NB) ? g_bsum[t] : 0;
    s[t] = v;
    __syncthreads();
#pragma unroll
    for (int off = 1; off < 256; off <<= 1) {
        int x = (t >= off) ? s[t - off] : 0;
        __syncthreads();
        s[t] += x;
        __syncthreads();
    }
    if (t < NB) g_bsum[t] = s[t] - v;
}
__global__ void k_scan_add() {
    int i = blockIdx.x * blockDim.x + threadIdx.x;
    if (i < NN) {
        int r = g_rowptr[i] + g_bsum[i / SCB];
        g_rowptr[i] = r;
        g_cursor[i] = r;
        g_dinv[i] = rsqrtf((float)(g_cnti[i] + 1));
    }
    if (i == 0) g_rowptr[NN] = EE;
}
__global__ void k_fill(const int* __restrict__ src, const int* __restrict__ dst) {
    int e = blockIdx.x * blockDim.x + threadIdx.x;
    if (e < EE) {
        int d = dst[e];
        int pos = atomicAdd(&g_cursor[d], 1);
        g_csr[pos] = src[e];
    }
}

// ---------------- fold: Wf = W1 @ We ----------------
__global__ void k_fold(const float* __restrict__ W1, const float* __restrict__ We) {
    __shared__ float we[DD * FF];
    int tid = threadIdx.x;
    for (int i = tid; i < DD * FF; i += 512) we[i] = We[i];
    __syncthreads();
    for (int i = tid; i < DD * FF; i += 512) {
        int d = i >> 4, f = i & 15;
        float s = 0.f;
#pragma unroll 8
        for (int k = 0; k < DD; k++) s += W1[d * DD + k] * we[k * FF + f];
        g_wf[i] = s;
    }
}

// ---------------- layer0 transform: m = dinv * (x @ Wf^T), bf16 packed out ----------------
__global__ void k_gemm16(const float* __restrict__ x) {
    __shared__ float wt[FF * DD];   // wt[f*128 + d]
    __shared__ float xs[32 * FF];
    int tid = threadIdx.x;
    for (int idx = tid; idx < DD * FF; idx += 256) {
        int d = idx >> 4, f = idx & 15;
        wt[f * DD + d] = g_wf[idx];
    }
    int n0 = blockIdx.x * 32;
    for (int idx = tid; idx < 32 * FF; idx += 256) xs[idx] = x[(size_t)n0 * FF + idx];
    __syncthreads();

    int p = tid & 63;
    int nb = tid >> 6;
    int d0 = 2 * p;
#pragma unroll
    for (int it = 0; it < 8; it++) {
        int n = it * 4 + nb;
        float s0 = 0.f, s1 = 0.f;
#pragma unroll
        for (int f = 0; f < FF; f++) {
            float xv = xs[n * FF + f];
            s0 = fmaf(xv, wt[f * DD + d0], s0);
            s1 = fmaf(xv, wt[f * DD + d0 + 1], s1);
        }
        float sc = g_dinv[n0 + n];
        g_mb[(size_t)(n0 + n) * 64 + p] = f2bf2(s0 * sc, s1 * sc);
    }
}

// ---------------- GCN transform (bf16 tensor cores): m = dinv * (h @ W^T), bf16 out ----------------
__global__ void __launch_bounds__(256, 2) k_gemm_tc(const float* __restrict__ W) {
    __shared__ u32 Ws[DD][PAD];   // bf16x2 words, Ws[dout][w]
    __shared__ u32 hs[DD][PAD];   // bf16x2 words, hs[row][w]
    int tid = threadIdx.x;
    int warp = tid >> 5, lane = tid & 31;
    int lq = lane >> 2, lr = lane & 3;
    int n0 = blockIdx.x * 128;
    int wr = warp * 16;

    float acc[16][4];
#pragma unroll
    for (int t = 0; t < 16; t++)
#pragma unroll
        for (int q = 0; q < 4; q++) acc[t][q] = 0.f;

    for (int kc = 0; kc < DD; kc += KC) {
        for (int idx = tid; idx < DD * (KC / 2); idx += 256) {
            int r = idx >> 5, w = idx & 31;
            float2 wv = *(const float2*)&W[r * DD + kc + 2 * w];
            Ws[r][w] = f2bf2(wv.x, wv.y);
            int n = n0 + r;
            hs[r][w] = (n < NN) ? g_hb[(size_t)n * 64 + (kc >> 1) + w] : 0u;
        }
        __syncthreads();
#pragma unroll
        for (int kq = 0; kq < KC / 16; kq++) {
            u32 a0 = hs[wr + lq][kq * 8 + lr];
            u32 a1 = hs[wr + lq + 8][kq * 8 + lr];
            u32 a2 = hs[wr + lq][kq * 8 + lr + 4];
            u32 a3 = hs[wr + lq + 8][kq * 8 + lr + 4];
#pragma unroll
            for (int t = 0; t < 16; t++) {
                u32 b0 = Ws[t * 8 + lq][kq * 8 + lr];
                u32 b1 = Ws[t * 8 + lq][kq * 8 + lr + 4];
                mma_bf16(acc[t], a0, a1, a2, a3, b0, b1);
            }
        }
        __syncthreads();
    }

    int r0 = n0 + wr + lq, r1 = r0 + 8;
    float s0 = (r0 < NN) ? g_dinv[r0] : 0.f;
    float s1 = (r1 < NN) ? g_dinv[r1] : 0.f;
#pragma unroll
    for (int t = 0; t < 16; t++) {
        if (r0 < NN) g_mb[(size_t)r0 * 64 + t * 4 + lr] = f2bf2(acc[t][0] * s0, acc[t][1] * s0);
        if (r1 < NN) g_mb[(size_t)r1 * 64 + t * 4 + lr] = f2bf2(acc[t][2] * s1, acc[t][3] * s1);
    }
}

// ---------------- gather: warp per node, 2 edges in flight, bf16 in / bf16 out ----------------
#define ACC8(r) { \
    float2 q0 = bf2f((r).x), q1 = bf2f((r).y), q2 = bf2f((r).z), q3 = bf2f((r).w); \
    a0 += q0.x; a1 += q0.y; a2 += q1.x; a3 += q1.y; \
    a4 += q2.x; a5 += q2.y; a6 += q3.x; a7 += q3.y; }

__global__ void k_gather() {
    int w = (blockIdx.x * 256 + threadIdx.x) >> 5;
    int lane = threadIdx.x & 31;
    int half = lane >> 4, l16 = lane & 15;
    if (w >= NN) return;
    const uint4* M4 = (const uint4*)g_mb;   // row = 16 uint4; lane covers slot l16 of edge j+half

    float a0 = 0.f, a1 = 0.f, a2 = 0.f, a3 = 0.f;
    float a4 = 0.f, a5 = 0.f, a6 = 0.f, a7 = 0.f;
    if (half == 0) {
        uint4 sr = M4[(size_t)w * 16 + l16];
        ACC8(sr)
    }

    int i = g_rowptr[w];
    int cnt = g_rowptr[w + 1] - i;
    while (cnt > 0) {
        int take = cnt > 32 ? 32 : cnt;
        int nb = (lane < take) ? g_csr[i + lane] : 0;
        int j = 0;
        for (; j + 8 <= take; j += 8) {
            int u0 = __shfl_sync(0xffffffffu, nb, j + half);
            int u1 = __shfl_sync(0xffffffffu, nb, j + 2 + half);
            int u2 = __shfl_sync(0xffffffffu, nb, j + 4 + half);
            int u3 = __shfl_sync(0xffffffffu, nb, j + 6 + half);
            uint4 r0 = M4[(size_t)u0 * 16 + l16];
            uint4 r1 = M4[(size_t)u1 * 16 + l16];
            uint4 r2 = M4[(size_t)u2 * 16 + l16];
            uint4 r3 = M4[(size_t)u3 * 16 + l16];
            ACC8(r0) ACC8(r1) ACC8(r2) ACC8(r3)
        }
        for (; j < take; j += 2) {
            int jj = j + half;
            int u = __shfl_sync(0xffffffffu, nb, jj < 31 ? jj : 31);
            if (jj < take) {
                uint4 r = M4[(size_t)u * 16 + l16];
                ACC8(r)
            }
        }
        i += take;
        cnt -= take;
    }

    a0 += __shfl_xor_sync(0xffffffffu, a0, 16);
    a1 += __shfl_xor_sync(0xffffffffu, a1, 16);
    a2 += __shfl_xor_sync(0xffffffffu, a2, 16);
    a3 += __shfl_xor_sync(0xffffffffu, a3, 16);
    a4 += __shfl_xor_sync(0xffffffffu, a4, 16);
    a5 += __shfl_xor_sync(0xffffffffu, a5, 16);
    a6 += __shfl_xor_sync(0xffffffffu, a6, 16);
    a7 += __shfl_xor_sync(0xffffffffu, a7, 16);

    if (half == 0) {
        float sc = g_dinv[w];
        uint4 ov;
        ov.x = f2bf2(fmaxf(a0 * sc, 0.f), fmaxf(a1 * sc, 0.f));
        ov.y = f2bf2(fmaxf(a2 * sc, 0.f), fmaxf(a3 * sc, 0.f));
        ov.z = f2bf2(fmaxf(a4 * sc, 0.f), fmaxf(a5 * sc, 0.f));
        ov.w = f2bf2(fmaxf(a6 * sc, 0.f), fmaxf(a7 * sc, 0.f));
        ((uint4*)g_hb)[(size_t)w * 16 + l16] = ov;
    }
}

// ---------------- distances + pool (bf16 tensor cores): d2 = x2 + c2 - 2 h.c ----------------
#define DP_SMEM (DD * 132 * 4 + 3 * DD * 4)
__global__ void __launch_bounds__(256, 2) k_distpool_tc(const float* __restrict__ cent,
                                                        const int* __restrict__ batch) {
    extern __shared__ float dsm[];
    u32* cs = (u32*)dsm;                   // [128][36] bf16x2 words
    u32* hs = cs + DD * PAD;               // [128][36]
    float* dist = dsm;                     // [128][132] (phase 2)
    float* sx2 = dsm + DD * 132;
    float* sc2 = sx2 + DD;
    int*   sg  = (int*)(sc2 + DD);

    int tid = threadIdx.x;
    int warp = tid >> 5, lane = tid & 31;
    int lq = lane >> 2, lr = lane & 3;
    int n0 = blockIdx.x * 128;
    int wr = warp * 16;

    if (tid < DD) {
        sx2[tid] = 0.f;
        sc2[tid] = 0.f;
        int n = n0 + tid;
        sg[tid] = (n < NN) ? batch[n] : -1;
    }

    float acc[16][4];
#pragma unroll
    for (int t = 0; t < 16; t++)
#pragma unroll
        for (int q = 0; q < 4; q++) acc[t][q] = 0.f;

    for (int kc = 0; kc < DD; kc += KC) {
        for (int idx = tid; idx < DD * (KC / 2); idx += 256) {
            int r = idx >> 5, w = idx & 31;
            u32 cw = 0u;
            if (r < CC) {
                float2 cv = *(const float2*)&cent[r * DD + kc + 2 * w];
                cw = f2bf2(cv.x, cv.y);
            }
            cs[r * PAD + w] = cw;
            int n = n0 + r;
            hs[r * PAD + w] = (n < NN) ? g_hb[(size_t)n * 64 + (kc >> 1) + w] : 0u;
        }
        __syncthreads();
#pragma unroll
        for (int kq = 0; kq < KC / 16; kq++) {
            u32 a0 = hs[(wr + lq) * PAD + kq * 8 + lr];
            u32 a1 = hs[(wr + lq + 8) * PAD + kq * 8 + lr];
            u32 a2 = hs[(wr + lq) * PAD + kq * 8 + lr + 4];
            u32 a3 = hs[(wr + lq + 8) * PAD + kq * 8 + lr + 4];
#pragma unroll
            for (int t = 0; t < 16; t++) {
                u32 b0 = cs[(t * 8 + lq) * PAD + kq * 8 + lr];
                u32 b1 = cs[(t * 8 + lq) * PAD + kq * 8 + lr + 4];
                mma_bf16(acc[t], a0, a1, a2, a3, b0, b1);
            }
        }
        // norms from the SAME bf16-rounded values (keeps d2 = |a-c|^2 exact in fp32)
        if (tid < DD) {
            float sh = 0.f, sc = 0.f;
#pragma unroll 8
            for (int kk = 0; kk < KC / 2; kk++) {
                float2 hv = bf2f(hs[tid * PAD + kk]);
                float2 cv = bf2f(cs[tid * PAD + kk]);
                sh = fmaf(hv.x, hv.x, sh); sh = fmaf(hv.y, hv.y, sh);
                sc = fmaf(cv.x, cv.x, sc); sc = fmaf(cv.y, cv.y, sc);
            }
            sx2[tid] += sh;
            sc2[tid] += sc;
        }
        __syncthreads();
    }

    int R0 = wr + lq, R1 = R0 + 8;
    float x0 = sx2[R0], x1 = sx2[R1];
#pragma unroll
    for (int t = 0; t < 16; t++) {
        int c = t * 8 + 2 * lr;
        float c2a = sc2[c], c2b = sc2[c + 1];
        float d0 = sqrtf(fmaxf(x0 + c2a - 2.f * acc[t][0], 0.f) + 1e-12f);
        float d1 = sqrtf(fmaxf(x0 + c2b - 2.f * acc[t][1], 0.f) + 1e-12f);
        float d2 = sqrtf(fmaxf(x1 + c2a - 2.f * acc[t][2], 0.f) + 1e-12f);
        float d3 = sqrtf(fmaxf(x1 + c2b - 2.f * acc[t][3], 0.f) + 1e-12f);
        *(float2*)&dist[R0 * 132 + c] = make_float2(d0, d1);
        *(float2*)&dist[R1 * 132 + c] = make_float2(d2, d3);
    }
    __syncthreads();

    int c = tid & 127, half = tid >> 7;
    if (c < CC) {
        int rbeg = half * 64, rend = rbeg + 64;
        int cur = -2;
        float s = 0.f;
        for (int r = rbeg; r < rend; r++) {
            int g = sg[r];
            if (g < 0) break;
            float v = dist[r * 132 + c];
            if (g == cur) s += v;
            else {
                if (cur >= 0) atomicAdd(&g_pool[cur * CC + c], s);
                cur = g; s = v;
            }
        }
        if (cur >= 0) atomicAdd(&g_pool[cur * CC + c], s);
    }
}

// ---------------- output ----------------
__global__ void k_out(const float* __restrict__ Wout, const float* __restrict__ bout,
                      float* __restrict__ out) {
    int i = blockIdx.x * blockDim.x + threadIdx.x;
    if (i < GG * KK) {
        int g = i / KK, k = i % KK;
        float inv = 1.0f / fmaxf(g_cnt[g], 1.0f);
        float s = 0.f;
#pragma unroll 4
        for (int c = 0; c < CC; c++) s += g_pool[g * CC + c] * Wout[k * CC + c];
        out[i] = s * inv + bout[k];
    }
}

extern "C" void kernel_launch(void* const* d_in, const int* in_sizes, int n_in,
                              void* d_out, int out_size) {
    const float* x     = (const float*)d_in[0];
    const int*   ei    = (const int*)d_in[1];
    const int*   batch = (const int*)d_in[2];
    const float* We    = (const float*)d_in[3];
    const float* Wc    = (const float*)d_in[4];
    const float* cent  = (const float*)d_in[5];
    const float* Wout  = (const float*)d_in[6];
    const float* bout  = (const float*)d_in[7];
    float* out = (float*)d_out;

    const int* src = ei;
    const int* dst = ei + EE;

    cudaFuncSetAttribute(k_distpool_tc, cudaFuncAttributeMaxDynamicSharedMemorySize, DP_SMEM);

    const int T = 256;
    int zmax = (NN > GG * CC) ? NN : GG * CC;
    const int GB = (NN + 127) / 128;
    const int GATHB = (NN * 32 + T - 1) / T;

    k_zero<<<(zmax + T - 1) / T, T>>>();
    k_count<<<(EE + T - 1) / T, T>>>(dst, batch);
    k_scan_part<<<NB, SCB>>>();
    k_scan_bsum<<<1, 256>>>();
    k_scan_add<<<(NN + T - 1) / T, T>>>();
    k_fill<<<(EE + T - 1) / T, T>>>(src, dst);

    k_fold<<<1, 512>>>(Wc, We);
    k_gemm16<<<NN / 32, T>>>(x);
    k_gather<<<GATHB, T>>>();

    for (int l = 1; l < LL; l++) {
        k_gemm_tc<<<GB, T>>>(Wc + (size_t)l * DD * DD);
        k_gather<<<GATHB, T>>>();
    }

    k_distpool_tc<<<GB, T, DP_SMEM>>>(cent, batch);

    k_out<<<(GG * KK + T - 1) / T, T>>>(Wout, bout, out);
}